// round 1
// baseline (speedup 1.0000x reference)
#include <cuda_runtime.h>
#include <math.h>

// Problem constants
#define Bb   2
#define Ll   2048
#define Dd   1024
#define Hh   16
#define HDd  64
#define Mtot (Bb * Ll)          // 4096
#define SCALE 0.125f            // 1/sqrt(64)

// Scratch (no allocations allowed): q/k/v in [B,H,L,HD], ctx in [B,L,D]
__device__ float g_q[(size_t)Bb * Hh * Ll * HDd];
__device__ float g_k[(size_t)Bb * Hh * Ll * HDd];
__device__ float g_v[(size_t)Bb * Hh * Ll * HDd];
__device__ float g_ctx[(size_t)Bb * Ll * Dd];

// ---------------------------------------------------------------------------
// GEMM: out[m,n] = sum_k A[m,k] * W[n,k]  (+ bias[n])
// M=4096, N=1024, K=1024 fixed. 128x128 tile, BK=8, 256 threads, 8x8 per thread.
// MODE 0/1/2: A = param (Q/K/V input), OUT = g_q/g_k/g_v written in [B,H,L,HD]
// MODE 3:     A = g_ctx,               OUT = param ([M,N] contiguous) + bias
// ---------------------------------------------------------------------------
template <int MODE>
__global__ __launch_bounds__(256, 2)
void gemm_nt_kernel(const float* __restrict__ Aparam,
                    const float* __restrict__ W,
                    const float* __restrict__ bias,
                    float* __restrict__ outParam)
{
    constexpr int BM = 128, BN = 128, BK = 8;
    constexpr int Kdim = 1024;

    const float* A = (MODE == 3) ? (const float*)g_ctx : Aparam;
    float* out = (MODE == 0) ? g_q : (MODE == 1) ? g_k : (MODE == 2) ? g_v : outParam;

    __shared__ float As[BK][BM];
    __shared__ float Bs[BK][BN];

    const int tid = threadIdx.x;
    const int ty = tid >> 4;          // 0..15
    const int tx = tid & 15;          // 0..15
    const int m0 = blockIdx.y * BM;
    const int n0 = blockIdx.x * BN;

    float acc[8][8];
#pragma unroll
    for (int r = 0; r < 8; r++)
#pragma unroll
        for (int c = 0; c < 8; c++) acc[r][c] = 0.0f;

    // loader mapping: 256 threads cover 128 rows x (8 floats = 2 float4)
    const int lrow = tid >> 1;           // 0..127
    const int lk4  = (tid & 1) << 2;     // 0 or 4
    const float* Aptr = A + (size_t)(m0 + lrow) * Kdim + lk4;
    const float* Wptr = W + (size_t)(n0 + lrow) * Kdim + lk4;

    for (int k0 = 0; k0 < Kdim; k0 += BK) {
        float4 av = *(const float4*)(Aptr + k0);
        float4 bv = *(const float4*)(Wptr + k0);
        __syncthreads();   // previous tile's compute done
        As[lk4 + 0][lrow] = av.x; As[lk4 + 1][lrow] = av.y;
        As[lk4 + 2][lrow] = av.z; As[lk4 + 3][lrow] = av.w;
        Bs[lk4 + 0][lrow] = bv.x; Bs[lk4 + 1][lrow] = bv.y;
        Bs[lk4 + 2][lrow] = bv.z; Bs[lk4 + 3][lrow] = bv.w;
        __syncthreads();

#pragma unroll
        for (int kk = 0; kk < BK; kk++) {
            float4 a0 = *(const float4*)&As[kk][ty * 8];
            float4 a1 = *(const float4*)&As[kk][ty * 8 + 4];
            float4 b0 = *(const float4*)&Bs[kk][tx * 8];
            float4 b1 = *(const float4*)&Bs[kk][tx * 8 + 4];
            float ar[8] = {a0.x, a0.y, a0.z, a0.w, a1.x, a1.y, a1.z, a1.w};
            float br[8] = {b0.x, b0.y, b0.z, b0.w, b1.x, b1.y, b1.z, b1.w};
#pragma unroll
            for (int r = 0; r < 8; r++)
#pragma unroll
                for (int c = 0; c < 8; c++)
                    acc[r][c] = fmaf(ar[r], br[c], acc[r][c]);
        }
    }

    // store
    if (MODE != 3) {
        // remap (m,n) -> [B,H,L,HD]: m = b*L + l ; n = h*64 + hd
#pragma unroll
        for (int r = 0; r < 8; r++) {
            int m = m0 + ty * 8 + r;
            int b = m >> 11;
            int l = m & (Ll - 1);
#pragma unroll
            for (int half = 0; half < 2; half++) {
                int n  = n0 + tx * 8 + half * 4;
                int h  = n >> 6;
                int hd = n & 63;
                float* dst = out + ((((size_t)b * Hh + h) * Ll + l) * HDd + hd);
                *(float4*)dst = make_float4(acc[r][half * 4 + 0], acc[r][half * 4 + 1],
                                            acc[r][half * 4 + 2], acc[r][half * 4 + 3]);
            }
        }
    } else {
#pragma unroll
        for (int r = 0; r < 8; r++) {
            int m = m0 + ty * 8 + r;
            float* dst = out + (size_t)m * 1024 + n0 + tx * 8;
#pragma unroll
            for (int half = 0; half < 2; half++) {
                int n = n0 + tx * 8 + half * 4;
                float4 bb = *(const float4*)(bias + n);
                *(float4*)(dst + half * 4) =
                    make_float4(acc[r][half * 4 + 0] + bb.x, acc[r][half * 4 + 1] + bb.y,
                                acc[r][half * 4 + 2] + bb.z, acc[r][half * 4 + 3] + bb.w);
            }
        }
    }
}

// ---------------------------------------------------------------------------
// Flash attention (causal), fp32, online softmax.
// Grid: (L/64, B*H). Block 256 threads (16x16).
// Q tile 64 rows, K/V tiles 32 rows. Writes context into [B,L,D].
// ---------------------------------------------------------------------------
__global__ __launch_bounds__(256)
void flash_attn_kernel()
{
    constexpr int BM = 64, BN = 32;
    __shared__ float Qs[HDd][BM + 4];   // [d][q], pad 4 for float4 loads
    __shared__ float Ks[HDd][BN + 2];   // [d][k], pad 2 for float2 loads
    __shared__ float Vs[BN][HDd + 4];   // [k][d]
    __shared__ float Ps[BM][BN + 1];    // [q][k]

    const int tid = threadIdx.x;
    const int ty = tid >> 4;   // 0..15 -> 4 query rows each
    const int tx = tid & 15;   // 0..15 -> 2 score cols / 4 O cols each
    const int q0 = blockIdx.x * BM;
    const int bh = blockIdx.y;
    const int b = bh >> 4;
    const int h = bh & (Hh - 1);

    const float* qb = g_q + (size_t)bh * Ll * HDd;
    const float* kb = g_k + (size_t)bh * Ll * HDd;
    const float* vb = g_v + (size_t)bh * Ll * HDd;

    // load Q tile [64 x 64] into Qs[d][q]
#pragma unroll
    for (int it = 0; it < 4; it++) {
        int idx = tid + it * 256;        // 0..1023
        int qq = idx >> 4;               // 0..63
        int d0 = (idx & 15) << 2;        // 0..60
        float4 val = *(const float4*)(qb + (size_t)(q0 + qq) * HDd + d0);
        Qs[d0 + 0][qq] = val.x; Qs[d0 + 1][qq] = val.y;
        Qs[d0 + 2][qq] = val.z; Qs[d0 + 3][qq] = val.w;
    }

    float m_i[4], l_i[4], acc[4][4];
#pragma unroll
    for (int r = 0; r < 4; r++) {
        m_i[r] = -1e30f; l_i[r] = 0.0f;
#pragma unroll
        for (int c = 0; c < 4; c++) acc[r][c] = 0.0f;
    }

    const int nTiles = (q0 + BM) / BN;   // causal: key tiles 0 .. q0/32+1

    for (int t = 0; t < nTiles; t++) {
        const int j0 = t * BN;
        // load K,V tiles [32 x 64]
#pragma unroll
        for (int it = 0; it < 2; it++) {
            int idx = tid + it * 256;    // 0..511
            int kk = idx >> 4;           // 0..31
            int d0 = (idx & 15) << 2;
            float4 kv = *(const float4*)(kb + (size_t)(j0 + kk) * HDd + d0);
            Ks[d0 + 0][kk] = kv.x; Ks[d0 + 1][kk] = kv.y;
            Ks[d0 + 2][kk] = kv.z; Ks[d0 + 3][kk] = kv.w;
            float4 vv = *(const float4*)(vb + (size_t)(j0 + kk) * HDd + d0);
            *(float4*)&Vs[kk][d0] = vv;
        }
        __syncthreads();

        // S = Q K^T fragment: 4 rows x 2 cols per thread
        float s[4][2] = {{0.f, 0.f}, {0.f, 0.f}, {0.f, 0.f}, {0.f, 0.f}};
#pragma unroll
        for (int d = 0; d < HDd; d++) {
            float4 qv = *(const float4*)&Qs[d][ty * 4];      // broadcast within warp
            float2 kv = *(const float2*)&Ks[d][tx * 2];
            s[0][0] = fmaf(qv.x, kv.x, s[0][0]); s[0][1] = fmaf(qv.x, kv.y, s[0][1]);
            s[1][0] = fmaf(qv.y, kv.x, s[1][0]); s[1][1] = fmaf(qv.y, kv.y, s[1][1]);
            s[2][0] = fmaf(qv.z, kv.x, s[2][0]); s[2][1] = fmaf(qv.z, kv.y, s[2][1]);
            s[3][0] = fmaf(qv.w, kv.x, s[3][0]); s[3][1] = fmaf(qv.w, kv.y, s[3][1]);
        }

        // scale + causal mask
#pragma unroll
        for (int r = 0; r < 4; r++) {
            int qi = q0 + ty * 4 + r;
#pragma unroll
            for (int c = 0; c < 2; c++) {
                int kj = j0 + tx * 2 + c;
                float sv = s[r][c] * SCALE;
                s[r][c] = (kj > qi) ? -1e30f : sv;
            }
        }

        // online softmax update (row groups = 16 contiguous lanes of a warp)
#pragma unroll
        for (int r = 0; r < 4; r++) {
            float mx = fmaxf(s[r][0], s[r][1]);
#pragma unroll
            for (int o = 8; o >= 1; o >>= 1)
                mx = fmaxf(mx, __shfl_xor_sync(0xffffffffu, mx, o));
            float mnew = fmaxf(m_i[r], mx);
            float p0 = __expf(s[r][0] - mnew);
            float p1 = __expf(s[r][1] - mnew);
            float ps = p0 + p1;
#pragma unroll
            for (int o = 8; o >= 1; o >>= 1)
                ps += __shfl_xor_sync(0xffffffffu, ps, o);
            float alpha = __expf(m_i[r] - mnew);
            l_i[r] = l_i[r] * alpha + ps;
            m_i[r] = mnew;
#pragma unroll
            for (int c = 0; c < 4; c++) acc[r][c] *= alpha;
            Ps[ty * 4 + r][tx * 2 + 0] = p0;
            Ps[ty * 4 + r][tx * 2 + 1] = p1;
        }
        __syncthreads();

        // O += P @ V : 4 rows x 4 O-cols per thread
#pragma unroll
        for (int kk = 0; kk < BN; kk++) {
            float4 vv = *(const float4*)&Vs[kk][tx * 4];
#pragma unroll
            for (int r = 0; r < 4; r++) {
                float p = Ps[ty * 4 + r][kk];     // broadcast within warp
                acc[r][0] = fmaf(p, vv.x, acc[r][0]);
                acc[r][1] = fmaf(p, vv.y, acc[r][1]);
                acc[r][2] = fmaf(p, vv.z, acc[r][2]);
                acc[r][3] = fmaf(p, vv.w, acc[r][3]);
            }
        }
        __syncthreads();
    }

    // normalize & write context in [B,L,D]
#pragma unroll
    for (int r = 0; r < 4; r++) {
        float inv = 1.0f / l_i[r];
        int l = q0 + ty * 4 + r;
        float* dst = g_ctx + ((size_t)b * Ll + l) * Dd + h * HDd + tx * 4;
        *(float4*)dst = make_float4(acc[r][0] * inv, acc[r][1] * inv,
                                    acc[r][2] * inv, acc[r][3] * inv);
    }
}

// ---------------------------------------------------------------------------
// Launch
// ---------------------------------------------------------------------------
extern "C" void kernel_launch(void* const* d_in, const int* in_sizes, int n_in,
                              void* d_out, int out_size)
{
    const float* Q  = (const float*)d_in[0];
    const float* K  = (const float*)d_in[1];
    const float* V  = (const float*)d_in[2];
    // d_in[3] = mask (causal tril, applied analytically)
    const float* wq = (const float*)d_in[4];
    const float* wk = (const float*)d_in[5];
    const float* wv = (const float*)d_in[6];
    const float* wo = (const float*)d_in[7];
    const float* bo = (const float*)d_in[8];
    float* out = (float*)d_out;

    dim3 ggrid(1024 / 128, Mtot / 128);   // (8, 32)

    gemm_nt_kernel<0><<<ggrid, 256>>>(Q, wq, nullptr, nullptr);
    gemm_nt_kernel<1><<<ggrid, 256>>>(K, wk, nullptr, nullptr);
    gemm_nt_kernel<2><<<ggrid, 256>>>(V, wv, nullptr, nullptr);

    flash_attn_kernel<<<dim3(Ll / 64, Bb * Hh), 256>>>();

    gemm_nt_kernel<3><<<ggrid, 256>>>(nullptr, wo, bo, out);
}

// round 3
// speedup vs baseline: 1.3963x; 1.3963x over previous
#include <cuda_runtime.h>
#include <math.h>
#include <cstdint>

// Problem constants
#define Bb   2
#define Ll   2048
#define Dd   1024
#define Hh   16
#define HDd  64
#define Mtot (Bb * Ll)          // 4096
#define SCALE 0.125f            // 1/sqrt(64)

// Scratch (no allocations allowed): q/k/v in [B,H,L,HD], ctx in [B,L,D]
__device__ float g_q[(size_t)Bb * Hh * Ll * HDd];
__device__ float g_k[(size_t)Bb * Hh * Ll * HDd];
__device__ float g_v[(size_t)Bb * Hh * Ll * HDd];
__device__ float g_ctx[(size_t)Bb * Ll * Dd];

__device__ __forceinline__ uint32_t cvt_tf32(float x) {
    uint32_t r;
    asm("cvt.rna.tf32.f32 %0, %1;" : "=r"(r) : "f"(x));
    return r;
}

__device__ __forceinline__ void mma_tf32(float* d, const uint32_t* a, const uint32_t* b) {
    asm volatile(
        "mma.sync.aligned.m16n8k8.row.col.f32.tf32.tf32.f32 "
        "{%0,%1,%2,%3}, {%4,%5,%6,%7}, {%8,%9}, {%0,%1,%2,%3};"
        : "+f"(d[0]), "+f"(d[1]), "+f"(d[2]), "+f"(d[3])
        : "r"(a[0]), "r"(a[1]), "r"(a[2]), "r"(a[3]), "r"(b[0]), "r"(b[1]));
}

// ---------------------------------------------------------------------------
// tf32 mma.sync GEMM: out[m,n] = sum_k A[m,k] * W[n,k] (+ bias)
// M=4096, N=1024, K=1024. CTA tile 128x128x32, 8 warps (2x4), warp 64x32.
// Smem: fragment-major double buffer, 2 * (A 16KB + B 16KB) = 64KB dynamic.
//   A frag: [kstep(4)][mtile(8)][reg(4)][g(8)][tig(4)]  (4096 u32)
//   B frag: [kstep(4)][ntile(16)][reg(2)][g(8)][tig(4)] (4096 u32, at +4096)
// remap=true: out written in [B,H,L,HD]; else [M,N] + bias.
// ---------------------------------------------------------------------------
#define GEMM_SMEM_BYTES 65536

__device__ __forceinline__ void gemm_body(const float* __restrict__ A,
                                          const float* __restrict__ W,
                                          const float* __restrict__ bias,
                                          float* __restrict__ out,
                                          bool remap)
{
    extern __shared__ uint32_t sbuf[];   // [2][8192]

    const int tid  = threadIdx.x;
    const int lane = tid & 31;
    const int wid  = tid >> 5;
    const int wm   = wid >> 2;          // 0..1
    const int wn   = wid & 3;           // 0..3
    const int g    = lane >> 2;         // 0..7
    const int tg   = lane & 3;          // 0..3

    const int m0 = blockIdx.y * 128;
    const int n0 = blockIdx.x * 128;

    // loader mapping: per thread, rows mrow+32j (j=0..3), float4 col c
    const int mrow = tid >> 3;          // 0..31
    const int c    = tid & 7;           // float4 column within 32-wide k tile
    const int ks_  = c >> 1;
    const int ci   = c & 1;
    const int ri   = (mrow >> 3) & 1;
    const int gl   = mrow & 7;

    const float* Ap = A + (size_t)(m0 + mrow) * 1024 + c * 4;
    const float* Wp = W + (size_t)(n0 + mrow) * 1024 + c * 4;

    // smem store bases (u32 index); per j add 256
    const int sA = (((ks_ * 8 + (mrow >> 4)) * 4 + (ri + 2 * ci)) * 8 + gl) * 4;
    const int sB = 4096 + (((ks_ * 16 + (mrow >> 3)) * 2 + ci) * 8 + gl) * 4;

    float acc[4][4][4];
#pragma unroll
    for (int mt = 0; mt < 4; mt++)
#pragma unroll
        for (int nt = 0; nt < 4; nt++)
#pragma unroll
            for (int r = 0; r < 4; r++) acc[mt][nt][r] = 0.0f;

    uint4 ra[4], rb[4];

    auto gload = [&](int kt) {
#pragma unroll
        for (int j = 0; j < 4; j++) {
            float4 fa = *(const float4*)(Ap + kt * 32 + j * 32768);
            ra[j].x = cvt_tf32(fa.x); ra[j].y = cvt_tf32(fa.y);
            ra[j].z = cvt_tf32(fa.z); ra[j].w = cvt_tf32(fa.w);
            float4 fw = *(const float4*)(Wp + kt * 32 + j * 32768);
            rb[j].x = cvt_tf32(fw.x); rb[j].y = cvt_tf32(fw.y);
            rb[j].z = cvt_tf32(fw.z); rb[j].w = cvt_tf32(fw.w);
        }
    };
    auto sstore = [&](uint32_t* buf) {
#pragma unroll
        for (int j = 0; j < 4; j++) {
            *(uint4*)&buf[sA + j * 256] = ra[j];
            *(uint4*)&buf[sB + j * 256] = rb[j];
        }
    };

    gload(0);
    sstore(sbuf);

    for (int kt = 0; kt < 32; kt++) {
        uint32_t* cur = sbuf + (kt & 1) * 8192;
        if (kt < 31) gload(kt + 1);
        __syncthreads();

#pragma unroll
        for (int ks = 0; ks < 4; ks++) {
            uint32_t af[4][4];
#pragma unroll
            for (int mt = 0; mt < 4; mt++) {
                const int base = ((ks * 8 + wm * 4 + mt) * 4) * 32 + g * 4 + tg;
#pragma unroll
                for (int r = 0; r < 4; r++) af[mt][r] = cur[base + r * 32];
            }
            uint32_t bf[4][2];
#pragma unroll
            for (int nt = 0; nt < 4; nt++) {
                const int base = 4096 + ((ks * 16 + wn * 4 + nt) * 2) * 32 + g * 4 + tg;
#pragma unroll
                for (int r = 0; r < 2; r++) bf[nt][r] = cur[base + r * 32];
            }
#pragma unroll
            for (int mt = 0; mt < 4; mt++)
#pragma unroll
                for (int nt = 0; nt < 4; nt++)
                    mma_tf32(acc[mt][nt], af[mt], bf[nt]);
        }

        if (kt < 31) {
            __syncthreads();
            sstore(sbuf + ((kt + 1) & 1) * 8192);
        }
    }

    // epilogue
#pragma unroll
    for (int mt = 0; mt < 4; mt++) {
#pragma unroll
        for (int nt = 0; nt < 4; nt++) {
            const int m = m0 + wm * 64 + mt * 16 + g;
            const int n = n0 + wn * 32 + nt * 8 + tg * 2;
            float2 lo = make_float2(acc[mt][nt][0], acc[mt][nt][1]);
            float2 hi = make_float2(acc[mt][nt][2], acc[mt][nt][3]);
            if (remap) {
                const int h  = n >> 6;
                const int hd = n & 63;
                const int b0_ = m >> 11,      l0 = m & 2047;
                const int b1_ = (m + 8) >> 11, l1 = (m + 8) & 2047;
                *(float2*)(out + (((size_t)(b0_ * Hh + h) * Ll + l0) * HDd + hd)) = lo;
                *(float2*)(out + (((size_t)(b1_ * Hh + h) * Ll + l1) * HDd + hd)) = hi;
            } else {
                float2 bb = make_float2(bias[n], bias[n + 1]);
                lo.x += bb.x; lo.y += bb.y; hi.x += bb.x; hi.y += bb.y;
                *(float2*)(out + (size_t)m * 1024 + n) = lo;
                *(float2*)(out + (size_t)(m + 8) * 1024 + n) = hi;
            }
        }
    }
}

__global__ __launch_bounds__(256)
void gemm_qkv(const float* __restrict__ Q, const float* __restrict__ K,
              const float* __restrict__ V, const float* __restrict__ wq,
              const float* __restrict__ wk, const float* __restrict__ wv)
{
    const int z = blockIdx.z;
    const float* A = (z == 0) ? Q : (z == 1) ? K : V;
    const float* W = (z == 0) ? wq : (z == 1) ? wk : wv;
    float* out = (z == 0) ? g_q : (z == 1) ? g_k : g_v;
    gemm_body(A, W, nullptr, out, true);
}

__global__ __launch_bounds__(256)
void gemm_o(const float* __restrict__ wo, const float* __restrict__ bo,
            float* __restrict__ out)
{
    gemm_body(g_ctx, wo, bo, out, false);
}

// ---------------------------------------------------------------------------
// Flash attention (causal), fp32, online softmax. (unchanged from R1)
// ---------------------------------------------------------------------------
__global__ __launch_bounds__(256)
void flash_attn_kernel()
{
    constexpr int BM = 64, BN = 32;
    __shared__ float Qs[HDd][BM + 4];
    __shared__ float Ks[HDd][BN + 2];
    __shared__ float Vs[BN][HDd + 4];
    __shared__ float Ps[BM][BN + 1];

    const int tid = threadIdx.x;
    const int ty = tid >> 4;
    const int tx = tid & 15;
    const int q0 = blockIdx.x * BM;
    const int bh = blockIdx.y;
    const int b = bh >> 4;
    const int h = bh & (Hh - 1);

    const float* qb = g_q + (size_t)bh * Ll * HDd;
    const float* kb = g_k + (size_t)bh * Ll * HDd;
    const float* vb = g_v + (size_t)bh * Ll * HDd;

#pragma unroll
    for (int it = 0; it < 4; it++) {
        int idx = tid + it * 256;
        int qq = idx >> 4;
        int d0 = (idx & 15) << 2;
        float4 val = *(const float4*)(qb + (size_t)(q0 + qq) * HDd + d0);
        Qs[d0 + 0][qq] = val.x; Qs[d0 + 1][qq] = val.y;
        Qs[d0 + 2][qq] = val.z; Qs[d0 + 3][qq] = val.w;
    }

    float m_i[4], l_i[4], acc[4][4];
#pragma unroll
    for (int r = 0; r < 4; r++) {
        m_i[r] = -1e30f; l_i[r] = 0.0f;
#pragma unroll
        for (int c = 0; c < 4; c++) acc[r][c] = 0.0f;
    }

    const int nTiles = (q0 + BM) / BN;

    for (int t = 0; t < nTiles; t++) {
        const int j0 = t * BN;
#pragma unroll
        for (int it = 0; it < 2; it++) {
            int idx = tid + it * 256;
            int kk = idx >> 4;
            int d0 = (idx & 15) << 2;
            float4 kv = *(const float4*)(kb + (size_t)(j0 + kk) * HDd + d0);
            Ks[d0 + 0][kk] = kv.x; Ks[d0 + 1][kk] = kv.y;
            Ks[d0 + 2][kk] = kv.z; Ks[d0 + 3][kk] = kv.w;
            float4 vv = *(const float4*)(vb + (size_t)(j0 + kk) * HDd + d0);
            *(float4*)&Vs[kk][d0] = vv;
        }
        __syncthreads();

        float s[4][2] = {{0.f, 0.f}, {0.f, 0.f}, {0.f, 0.f}, {0.f, 0.f}};
#pragma unroll
        for (int d = 0; d < HDd; d++) {
            float4 qv = *(const float4*)&Qs[d][ty * 4];
            float2 kv = *(const float2*)&Ks[d][tx * 2];
            s[0][0] = fmaf(qv.x, kv.x, s[0][0]); s[0][1] = fmaf(qv.x, kv.y, s[0][1]);
            s[1][0] = fmaf(qv.y, kv.x, s[1][0]); s[1][1] = fmaf(qv.y, kv.y, s[1][1]);
            s[2][0] = fmaf(qv.z, kv.x, s[2][0]); s[2][1] = fmaf(qv.z, kv.y, s[2][1]);
            s[3][0] = fmaf(qv.w, kv.x, s[3][0]); s[3][1] = fmaf(qv.w, kv.y, s[3][1]);
        }

#pragma unroll
        for (int r = 0; r < 4; r++) {
            int qi = q0 + ty * 4 + r;
#pragma unroll
            for (int c = 0; c < 2; c++) {
                int kj = j0 + tx * 2 + c;
                float sv = s[r][c] * SCALE;
                s[r][c] = (kj > qi) ? -1e30f : sv;
            }
        }

#pragma unroll
        for (int r = 0; r < 4; r++) {
            float mx = fmaxf(s[r][0], s[r][1]);
#pragma unroll
            for (int o = 8; o >= 1; o >>= 1)
                mx = fmaxf(mx, __shfl_xor_sync(0xffffffffu, mx, o));
            float mnew = fmaxf(m_i[r], mx);
            float p0 = __expf(s[r][0] - mnew);
            float p1 = __expf(s[r][1] - mnew);
            float ps = p0 + p1;
#pragma unroll
            for (int o = 8; o >= 1; o >>= 1)
                ps += __shfl_xor_sync(0xffffffffu, ps, o);
            float alpha = __expf(m_i[r] - mnew);
            l_i[r] = l_i[r] * alpha + ps;
            m_i[r] = mnew;
#pragma unroll
            for (int c = 0; c < 4; c++) acc[r][c] *= alpha;
            Ps[ty * 4 + r][tx * 2 + 0] = p0;
            Ps[ty * 4 + r][tx * 2 + 1] = p1;
        }
        __syncthreads();

#pragma unroll
        for (int kk = 0; kk < BN; kk++) {
            float4 vv = *(const float4*)&Vs[kk][tx * 4];
#pragma unroll
            for (int r = 0; r < 4; r++) {
                float p = Ps[ty * 4 + r][kk];
                acc[r][0] = fmaf(p, vv.x, acc[r][0]);
                acc[r][1] = fmaf(p, vv.y, acc[r][1]);
                acc[r][2] = fmaf(p, vv.z, acc[r][2]);
                acc[r][3] = fmaf(p, vv.w, acc[r][3]);
            }
        }
        __syncthreads();
    }

#pragma unroll
    for (int r = 0; r < 4; r++) {
        float inv = 1.0f / l_i[r];
        int l = q0 + ty * 4 + r;
        float* dst = g_ctx + ((size_t)b * Ll + l) * Dd + h * HDd + tx * 4;
        *(float4*)dst = make_float4(acc[r][0] * inv, acc[r][1] * inv,
                                    acc[r][2] * inv, acc[r][3] * inv);
    }
}

// ---------------------------------------------------------------------------
// Launch
// ---------------------------------------------------------------------------
extern "C" void kernel_launch(void* const* d_in, const int* in_sizes, int n_in,
                              void* d_out, int out_size)
{
    const float* Q  = (const float*)d_in[0];
    const float* K  = (const float*)d_in[1];
    const float* V  = (const float*)d_in[2];
    // d_in[3] = mask (causal tril, applied analytically)
    const float* wq = (const float*)d_in[4];
    const float* wk = (const float*)d_in[5];
    const float* wv = (const float*)d_in[6];
    const float* wo = (const float*)d_in[7];
    const float* bo = (const float*)d_in[8];
    float* out = (float*)d_out;

    cudaFuncSetAttribute(gemm_qkv, cudaFuncAttributeMaxDynamicSharedMemorySize, GEMM_SMEM_BYTES);
    cudaFuncSetAttribute(gemm_o,   cudaFuncAttributeMaxDynamicSharedMemorySize, GEMM_SMEM_BYTES);

    gemm_qkv<<<dim3(8, 32, 3), 256, GEMM_SMEM_BYTES>>>(Q, K, V, wq, wk, wv);

    flash_attn_kernel<<<dim3(Ll / 64, Bb * Hh), 256>>>();

    gemm_o<<<dim3(8, 32), 256, GEMM_SMEM_BYTES>>>(wo, bo, out);
}

// round 4
// speedup vs baseline: 1.8657x; 1.3361x over previous
#include <cuda_runtime.h>
#include <math.h>
#include <cstdint>

// Problem constants
#define Bb   2
#define Ll   2048
#define Dd   1024
#define Hh   16
#define HDd  64
#define Mtot (Bb * Ll)          // 4096
#define SCALE 0.125f            // 1/sqrt(64)

// Scratch: q/k/v in [B,H,L,HD], ctx in [B,L,D]
__device__ float g_q[(size_t)Bb * Hh * Ll * HDd];
__device__ float g_k[(size_t)Bb * Hh * Ll * HDd];
__device__ float g_v[(size_t)Bb * Hh * Ll * HDd];
__device__ float g_ctx[(size_t)Bb * Ll * Dd];

__device__ __forceinline__ uint32_t cvt_tf32(float x) {
    uint32_t r;
    asm("cvt.rna.tf32.f32 %0, %1;" : "=r"(r) : "f"(x));
    return r;
}

__device__ __forceinline__ void mma_tf32(float* d, const uint32_t* a, const uint32_t* b) {
    asm volatile(
        "mma.sync.aligned.m16n8k8.row.col.f32.tf32.tf32.f32 "
        "{%0,%1,%2,%3}, {%4,%5,%6,%7}, {%8,%9}, {%0,%1,%2,%3};"
        : "+f"(d[0]), "+f"(d[1]), "+f"(d[2]), "+f"(d[3])
        : "r"(a[0]), "r"(a[1]), "r"(a[2]), "r"(a[3]), "r"(b[0]), "r"(b[1]));
}

__device__ __forceinline__ void mma_tf32_b(float* d, const uint32_t* a,
                                           uint32_t b0, uint32_t b1) {
    asm volatile(
        "mma.sync.aligned.m16n8k8.row.col.f32.tf32.tf32.f32 "
        "{%0,%1,%2,%3}, {%4,%5,%6,%7}, {%8,%9}, {%0,%1,%2,%3};"
        : "+f"(d[0]), "+f"(d[1]), "+f"(d[2]), "+f"(d[3])
        : "r"(a[0]), "r"(a[1]), "r"(a[2]), "r"(a[3]), "r"(b0), "r"(b1));
}

// ---------------------------------------------------------------------------
// tf32 mma.sync GEMM (unchanged from R3, known-good)
// ---------------------------------------------------------------------------
#define GEMM_SMEM_BYTES 65536

__device__ __forceinline__ void gemm_body(const float* __restrict__ A,
                                          const float* __restrict__ W,
                                          const float* __restrict__ bias,
                                          float* __restrict__ out,
                                          bool remap)
{
    extern __shared__ uint32_t sbuf[];   // [2][8192]

    const int tid  = threadIdx.x;
    const int lane = tid & 31;
    const int wid  = tid >> 5;
    const int wm   = wid >> 2;
    const int wn   = wid & 3;
    const int g    = lane >> 2;
    const int tg   = lane & 3;

    const int m0 = blockIdx.y * 128;
    const int n0 = blockIdx.x * 128;

    const int mrow = tid >> 3;
    const int c    = tid & 7;
    const int ks_  = c >> 1;
    const int ci   = c & 1;
    const int ri   = (mrow >> 3) & 1;
    const int gl   = mrow & 7;

    const float* Ap = A + (size_t)(m0 + mrow) * 1024 + c * 4;
    const float* Wp = W + (size_t)(n0 + mrow) * 1024 + c * 4;

    const int sA = (((ks_ * 8 + (mrow >> 4)) * 4 + (ri + 2 * ci)) * 8 + gl) * 4;
    const int sB = 4096 + (((ks_ * 16 + (mrow >> 3)) * 2 + ci) * 8 + gl) * 4;

    float acc[4][4][4];
#pragma unroll
    for (int mt = 0; mt < 4; mt++)
#pragma unroll
        for (int nt = 0; nt < 4; nt++)
#pragma unroll
            for (int r = 0; r < 4; r++) acc[mt][nt][r] = 0.0f;

    uint4 ra[4], rb[4];

    auto gload = [&](int kt) {
#pragma unroll
        for (int j = 0; j < 4; j++) {
            float4 fa = *(const float4*)(Ap + kt * 32 + j * 32768);
            ra[j].x = cvt_tf32(fa.x); ra[j].y = cvt_tf32(fa.y);
            ra[j].z = cvt_tf32(fa.z); ra[j].w = cvt_tf32(fa.w);
            float4 fw = *(const float4*)(Wp + kt * 32 + j * 32768);
            rb[j].x = cvt_tf32(fw.x); rb[j].y = cvt_tf32(fw.y);
            rb[j].z = cvt_tf32(fw.z); rb[j].w = cvt_tf32(fw.w);
        }
    };
    auto sstore = [&](uint32_t* buf) {
#pragma unroll
        for (int j = 0; j < 4; j++) {
            *(uint4*)&buf[sA + j * 256] = ra[j];
            *(uint4*)&buf[sB + j * 256] = rb[j];
        }
    };

    gload(0);
    sstore(sbuf);

    for (int kt = 0; kt < 32; kt++) {
        uint32_t* cur = sbuf + (kt & 1) * 8192;
        if (kt < 31) gload(kt + 1);
        __syncthreads();

#pragma unroll
        for (int ks = 0; ks < 4; ks++) {
            uint32_t af[4][4];
#pragma unroll
            for (int mt = 0; mt < 4; mt++) {
                const int base = ((ks * 8 + wm * 4 + mt) * 4) * 32 + g * 4 + tg;
#pragma unroll
                for (int r = 0; r < 4; r++) af[mt][r] = cur[base + r * 32];
            }
            uint32_t bf[4][2];
#pragma unroll
            for (int nt = 0; nt < 4; nt++) {
                const int base = 4096 + ((ks * 16 + wn * 4 + nt) * 2) * 32 + g * 4 + tg;
#pragma unroll
                for (int r = 0; r < 2; r++) bf[nt][r] = cur[base + r * 32];
            }
#pragma unroll
            for (int mt = 0; mt < 4; mt++)
#pragma unroll
                for (int nt = 0; nt < 4; nt++)
                    mma_tf32(acc[mt][nt], af[mt], bf[nt]);
        }

        if (kt < 31) {
            __syncthreads();
            sstore(sbuf + ((kt + 1) & 1) * 8192);
        }
    }

#pragma unroll
    for (int mt = 0; mt < 4; mt++) {
#pragma unroll
        for (int nt = 0; nt < 4; nt++) {
            const int m = m0 + wm * 64 + mt * 16 + g;
            const int n = n0 + wn * 32 + nt * 8 + tg * 2;
            float2 lo = make_float2(acc[mt][nt][0], acc[mt][nt][1]);
            float2 hi = make_float2(acc[mt][nt][2], acc[mt][nt][3]);
            if (remap) {
                const int h  = n >> 6;
                const int hd = n & 63;
                const int b0_ = m >> 11,       l0 = m & 2047;
                const int b1_ = (m + 8) >> 11, l1 = (m + 8) & 2047;
                *(float2*)(out + (((size_t)(b0_ * Hh + h) * Ll + l0) * HDd + hd)) = lo;
                *(float2*)(out + (((size_t)(b1_ * Hh + h) * Ll + l1) * HDd + hd)) = hi;
            } else {
                float2 bb = make_float2(bias[n], bias[n + 1]);
                lo.x += bb.x; lo.y += bb.y; hi.x += bb.x; hi.y += bb.y;
                *(float2*)(out + (size_t)m * 1024 + n) = lo;
                *(float2*)(out + (size_t)(m + 8) * 1024 + n) = hi;
            }
        }
    }
}

__global__ __launch_bounds__(256)
void gemm_qkv(const float* __restrict__ Q, const float* __restrict__ K,
              const float* __restrict__ V, const float* __restrict__ wq,
              const float* __restrict__ wk, const float* __restrict__ wv)
{
    const int z = blockIdx.z;
    const float* A = (z == 0) ? Q : (z == 1) ? K : V;
    const float* W = (z == 0) ? wq : (z == 1) ? wk : wv;
    float* out = (z == 0) ? g_q : (z == 1) ? g_k : g_v;
    gemm_body(A, W, nullptr, out, true);
}

__global__ __launch_bounds__(256)
void gemm_o(const float* __restrict__ wo, const float* __restrict__ bo,
            float* __restrict__ out)
{
    gemm_body(g_ctx, wo, bo, out, false);
}

// ---------------------------------------------------------------------------
// Tensor-core flash attention (causal), 3-term compensated tf32 (~fp32 acc).
// Grid (32 qblocks heavy-first, 32 bh), 128 threads (4 warps).
// Q tile 64 rows (warp w owns rows q0+w*16..+16), K/V tiles 64 rows.
// Smem (64KB dyn): Kh,Kl,Vh,Vl each 4096 u32, fragment-major, bank-swizzled:
//  K: idx = reg*2048 + (dc*8+nt)*32 + ((g ^ (reg*4 | (dc>>2)*2))*4) + (tg ^ (dc&3))
//     value K[j0 + nt*8 + g][dc*8 + tg + 4*reg]
//  V: idx = rv*2048 + (kc*8+ntd)*32 + ((g ^ (ntd&3))*4) + (tg ^ ((ntd&4)>>1))
//     value V[j0 + kc*8 + tg + 4*rv][ntd*8 + g]
// ---------------------------------------------------------------------------
#define FLASH_SMEM_BYTES 65536

__global__ __launch_bounds__(128)
void flash_tc()
{
    extern __shared__ uint32_t fs[];
    uint32_t* Kh = fs;
    uint32_t* Kl = fs + 4096;
    uint32_t* Vh = fs + 8192;
    uint32_t* Vl = fs + 12288;

    const int tid  = threadIdx.x;
    const int lane = tid & 31;
    const int w    = tid >> 5;
    const int g    = lane >> 2;
    const int tg   = lane & 3;

    const int qb = 31 - blockIdx.x;     // heavy blocks first
    const int q0 = qb * 64;
    const int bh = blockIdx.y;
    const int b  = bh >> 4;
    const int h  = bh & (Hh - 1);

    const float* qp = g_q + (size_t)bh * Ll * HDd;
    const float* kp = g_k + (size_t)bh * Ll * HDd;
    const float* vp = g_v + (size_t)bh * Ll * HDd;

    // ---- Q fragments (hi/lo), rows q0 + w*16 + {g, g+8}, one-time ----
    uint32_t qh[8][4], ql[8][4];
    {
        const float* q0p = qp + (size_t)(q0 + w * 16) * HDd;
#pragma unroll
        for (int dc = 0; dc < 8; dc++) {
            float v0 = q0p[g * 64 + dc * 8 + tg];
            float v1 = q0p[(g + 8) * 64 + dc * 8 + tg];
            float v2 = q0p[g * 64 + dc * 8 + tg + 4];
            float v3 = q0p[(g + 8) * 64 + dc * 8 + tg + 4];
            qh[dc][0] = cvt_tf32(v0); ql[dc][0] = cvt_tf32(v0 - __uint_as_float(qh[dc][0]));
            qh[dc][1] = cvt_tf32(v1); ql[dc][1] = cvt_tf32(v1 - __uint_as_float(qh[dc][1]));
            qh[dc][2] = cvt_tf32(v2); ql[dc][2] = cvt_tf32(v2 - __uint_as_float(qh[dc][2]));
            qh[dc][3] = cvt_tf32(v3); ql[dc][3] = cvt_tf32(v3 - __uint_as_float(qh[dc][3]));
        }
    }

    float m0 = -1e30f, m1 = -1e30f, l0 = 0.0f, l1 = 0.0f;
    float o[8][4];
#pragma unroll
    for (int nt = 0; nt < 8; nt++)
#pragma unroll
        for (int r = 0; r < 4; r++) o[nt][r] = 0.0f;

    const int nT = qb + 1;
    const int row0 = q0 + w * 16 + g;
    const int row1 = row0 + 8;

    for (int kt = 0; kt < nT; kt++) {
        const int j0 = kt * 64;
        __syncthreads();   // previous compute done before overwriting tiles

        // ---- load K/V tile (64x64 f32 each) into swizzled frag-major smem ----
#pragma unroll
        for (int i = 0; i < 8; i++) {
            const int t  = tid + i * 128;        // 0..1023
            const int j  = t >> 4;               // 0..63
            const int cq = t & 15;               // float4 col index
            const int d0 = cq * 4;

            float4 kv = *(const float4*)(kp + (size_t)(j0 + j) * 64 + d0);
            float4 vv = *(const float4*)(vp + (size_t)(j0 + j) * 64 + d0);

            // K store: dc = cq>>1, reg = cq&1
            {
                const int dc  = cq >> 1;
                const int reg = cq & 1;
                const int gsl = (j & 7) ^ ((reg << 2) | ((dc >> 2) << 1));
                const int base = reg * 2048 + (dc * 8 + (j >> 3)) * 32 + gsl * 4;
                const float kvv[4] = {kv.x, kv.y, kv.z, kv.w};
#pragma unroll
                for (int u = 0; u < 4; u++) {
                    const int idx = base + (u ^ (dc & 3));
                    uint32_t hi = cvt_tf32(kvv[u]);
                    Kh[idx] = hi;
                    Kl[idx] = cvt_tf32(kvv[u] - __uint_as_float(hi));
                }
            }
            // V store: kc = j>>3, rv = (j>>2)&1
            {
                const int kc = j >> 3;
                const int rv = (j >> 2) & 1;
                const float vvv[4] = {vv.x, vv.y, vv.z, vv.w};
#pragma unroll
                for (int u = 0; u < 4; u++) {
                    const int d   = d0 + u;
                    const int ntd = d >> 3;
                    const int idx = rv * 2048 + (kc * 8 + ntd) * 32
                                  + (((d & 7) ^ (ntd & 3)) << 2)
                                  + ((j & 3) ^ ((ntd & 4) >> 1));
                    uint32_t hi = cvt_tf32(vvv[u]);
                    Vh[idx] = hi;
                    Vl[idx] = cvt_tf32(vvv[u] - __uint_as_float(hi));
                }
            }
        }
        __syncthreads();

        // ---- S = Q K^T (compensated: qh*kh + qh*kl + ql*kh) ----
        float sc[8][4];
#pragma unroll
        for (int nt = 0; nt < 8; nt++)
#pragma unroll
            for (int r = 0; r < 4; r++) sc[nt][r] = 0.0f;

#pragma unroll
        for (int dc = 0; dc < 8; dc++) {
            const int tK = tg ^ (dc & 3);
            const int f0 = (dc >> 2) << 1;
            const int i0 = dc * 256 + ((g ^ f0) << 2) + tK;          // reg0 plane
            const int i1 = 2048 + dc * 256 + ((g ^ (f0 | 4)) << 2) + tK;
#pragma unroll
            for (int nt = 0; nt < 8; nt++) {
                const uint32_t bh0 = Kh[i0 + nt * 32];
                const uint32_t bh1 = Kh[i1 + nt * 32];
                const uint32_t bl0 = Kl[i0 + nt * 32];
                const uint32_t bl1 = Kl[i1 + nt * 32];
                mma_tf32_b(sc[nt], qh[dc], bh0, bh1);
                mma_tf32_b(sc[nt], qh[dc], bl0, bl1);
                mma_tf32_b(sc[nt], ql[dc], bh0, bh1);
            }
        }

        // ---- scale + causal mask (diagonal tile only) ----
        if (kt == nT - 1) {
#pragma unroll
            for (int nt = 0; nt < 8; nt++) {
                const int c0 = j0 + nt * 8 + tg * 2;
                const int c1 = c0 + 1;
                sc[nt][0] = (c0 <= row0) ? sc[nt][0] * SCALE : -1e30f;
                sc[nt][1] = (c1 <= row0) ? sc[nt][1] * SCALE : -1e30f;
                sc[nt][2] = (c0 <= row1) ? sc[nt][2] * SCALE : -1e30f;
                sc[nt][3] = (c1 <= row1) ? sc[nt][3] * SCALE : -1e30f;
            }
        } else {
#pragma unroll
            for (int nt = 0; nt < 8; nt++)
#pragma unroll
                for (int r = 0; r < 4; r++) sc[nt][r] *= SCALE;
        }

        // ---- online softmax (rows g / g+8; quad = 4 lanes share a row) ----
        float mx0 = -1e30f, mx1 = -1e30f;
#pragma unroll
        for (int nt = 0; nt < 8; nt++) {
            mx0 = fmaxf(mx0, fmaxf(sc[nt][0], sc[nt][1]));
            mx1 = fmaxf(mx1, fmaxf(sc[nt][2], sc[nt][3]));
        }
        mx0 = fmaxf(mx0, __shfl_xor_sync(0xffffffffu, mx0, 1));
        mx0 = fmaxf(mx0, __shfl_xor_sync(0xffffffffu, mx0, 2));
        mx1 = fmaxf(mx1, __shfl_xor_sync(0xffffffffu, mx1, 1));
        mx1 = fmaxf(mx1, __shfl_xor_sync(0xffffffffu, mx1, 2));

        const float mn0 = fmaxf(m0, mx0);
        const float mn1 = fmaxf(m1, mx1);
        const float a0 = __expf(m0 - mn0);
        const float a1 = __expf(m1 - mn1);

        float s0 = 0.0f, s1 = 0.0f;
#pragma unroll
        for (int nt = 0; nt < 8; nt++) {
            sc[nt][0] = __expf(sc[nt][0] - mn0);
            sc[nt][1] = __expf(sc[nt][1] - mn0);
            sc[nt][2] = __expf(sc[nt][2] - mn1);
            sc[nt][3] = __expf(sc[nt][3] - mn1);
            s0 += sc[nt][0] + sc[nt][1];
            s1 += sc[nt][2] + sc[nt][3];
        }
        s0 += __shfl_xor_sync(0xffffffffu, s0, 1);
        s0 += __shfl_xor_sync(0xffffffffu, s0, 2);
        s1 += __shfl_xor_sync(0xffffffffu, s1, 1);
        s1 += __shfl_xor_sync(0xffffffffu, s1, 2);

        l0 = l0 * a0 + s0;  m0 = mn0;
        l1 = l1 * a1 + s1;  m1 = mn1;

#pragma unroll
        for (int nt = 0; nt < 8; nt++) {
            o[nt][0] *= a0; o[nt][1] *= a0;
            o[nt][2] *= a1; o[nt][3] *= a1;
        }

        // ---- O += P V (compensated) ----
        const int sAsrc = (lane & ~3) | (tg >> 1);
        const int sBsrc = sAsrc + 2;
#pragma unroll
        for (int kc = 0; kc < 8; kc++) {
            uint32_t ph[4], pl[4];
#pragma unroll
            for (int r = 0; r < 4; r++) {
                ph[r] = cvt_tf32(sc[kc][r]);
                pl[r] = cvt_tf32(sc[kc][r] - __uint_as_float(ph[r]));
            }
            uint32_t ah[4], al[4];
            {
                uint32_t x0, x1;
                x0 = __shfl_sync(0xffffffffu, ph[0], sAsrc);
                x1 = __shfl_sync(0xffffffffu, ph[1], sAsrc);
                ah[0] = (tg & 1) ? x1 : x0;
                x0 = __shfl_sync(0xffffffffu, ph[2], sAsrc);
                x1 = __shfl_sync(0xffffffffu, ph[3], sAsrc);
                ah[1] = (tg & 1) ? x1 : x0;
                x0 = __shfl_sync(0xffffffffu, ph[0], sBsrc);
                x1 = __shfl_sync(0xffffffffu, ph[1], sBsrc);
                ah[2] = (tg & 1) ? x1 : x0;
                x0 = __shfl_sync(0xffffffffu, ph[2], sBsrc);
                x1 = __shfl_sync(0xffffffffu, ph[3], sBsrc);
                ah[3] = (tg & 1) ? x1 : x0;

                x0 = __shfl_sync(0xffffffffu, pl[0], sAsrc);
                x1 = __shfl_sync(0xffffffffu, pl[1], sAsrc);
                al[0] = (tg & 1) ? x1 : x0;
                x0 = __shfl_sync(0xffffffffu, pl[2], sAsrc);
                x1 = __shfl_sync(0xffffffffu, pl[3], sAsrc);
                al[1] = (tg & 1) ? x1 : x0;
                x0 = __shfl_sync(0xffffffffu, pl[0], sBsrc);
                x1 = __shfl_sync(0xffffffffu, pl[1], sBsrc);
                al[2] = (tg & 1) ? x1 : x0;
                x0 = __shfl_sync(0xffffffffu, pl[2], sBsrc);
                x1 = __shfl_sync(0xffffffffu, pl[3], sBsrc);
                al[3] = (tg & 1) ? x1 : x0;
            }
#pragma unroll
            for (int ntd = 0; ntd < 8; ntd++) {
                const int lv = ((g ^ (ntd & 3)) << 2) + (tg ^ ((ntd & 4) >> 1));
                const int i0 = kc * 256 + ntd * 32 + lv;
                const uint32_t bh0 = Vh[i0];
                const uint32_t bh1 = Vh[2048 + i0];
                const uint32_t bl0 = Vl[i0];
                const uint32_t bl1 = Vl[2048 + i0];
                mma_tf32_b(o[ntd], ah, bh0, bh1);
                mma_tf32_b(o[ntd], ah, bl0, bl1);
                mma_tf32_b(o[ntd], al, bh0, bh1);
            }
        }
    }

    // ---- normalize & write ctx[b, row, h*64 + hd] ----
    const float inv0 = 1.0f / l0;
    const float inv1 = 1.0f / l1;
    float* c0p = g_ctx + ((size_t)b * Ll + row0) * Dd + h * 64;
    float* c1p = g_ctx + ((size_t)b * Ll + row1) * Dd + h * 64;
#pragma unroll
    for (int nt = 0; nt < 8; nt++) {
        *(float2*)(c0p + nt * 8 + tg * 2) = make_float2(o[nt][0] * inv0, o[nt][1] * inv0);
        *(float2*)(c1p + nt * 8 + tg * 2) = make_float2(o[nt][2] * inv1, o[nt][3] * inv1);
    }
}

// ---------------------------------------------------------------------------
// Launch
// ---------------------------------------------------------------------------
extern "C" void kernel_launch(void* const* d_in, const int* in_sizes, int n_in,
                              void* d_out, int out_size)
{
    const float* Q  = (const float*)d_in[0];
    const float* K  = (const float*)d_in[1];
    const float* V  = (const float*)d_in[2];
    // d_in[3] = mask (causal tril, applied analytically)
    const float* wq = (const float*)d_in[4];
    const float* wk = (const float*)d_in[5];
    const float* wv = (const float*)d_in[6];
    const float* wo = (const float*)d_in[7];
    const float* bo = (const float*)d_in[8];
    float* out = (float*)d_out;

    cudaFuncSetAttribute(gemm_qkv, cudaFuncAttributeMaxDynamicSharedMemorySize, GEMM_SMEM_BYTES);
    cudaFuncSetAttribute(gemm_o,   cudaFuncAttributeMaxDynamicSharedMemorySize, GEMM_SMEM_BYTES);
    cudaFuncSetAttribute(flash_tc, cudaFuncAttributeMaxDynamicSharedMemorySize, FLASH_SMEM_BYTES);

    gemm_qkv<<<dim3(8, 32, 3), 256, GEMM_SMEM_BYTES>>>(Q, K, V, wq, wk, wv);

    flash_tc<<<dim3(32, 32), 128, FLASH_SMEM_BYTES>>>();

    gemm_o<<<dim3(8, 32), 256, GEMM_SMEM_BYTES>>>(wo, bo, out);
}

// round 5
// speedup vs baseline: 2.7133x; 1.4543x over previous
#include <cuda_runtime.h>
#include <math.h>
#include <cstdint>

// Problem constants
#define Bb   2
#define Ll   2048
#define Dd   1024
#define Hh   16
#define HDd  64
#define Mtot (Bb * Ll)          // 4096
#define SCALE 0.125f            // 1/sqrt(64)

// Scratch: q/k/v in [B,H,L,HD], ctx in [B,L,D]
__device__ float g_q[(size_t)Bb * Hh * Ll * HDd];
__device__ float g_k[(size_t)Bb * Hh * Ll * HDd];
__device__ float g_v[(size_t)Bb * Hh * Ll * HDd];
__device__ float g_ctx[(size_t)Bb * Ll * Dd];
// tf32-prerounded GEMM operands
__device__ float g_aq[(size_t)Mtot * Dd];
__device__ float g_ak[(size_t)Mtot * Dd];
__device__ float g_av[(size_t)Mtot * Dd];
__device__ float g_rw[(size_t)4 * Dd * Dd];

__device__ __forceinline__ uint32_t cvt_tf32(float x) {
    uint32_t r;
    asm("cvt.rna.tf32.f32 %0, %1;" : "=r"(r) : "f"(x));
    return r;
}

__device__ __forceinline__ uint32_t smem_u32(const void* p) {
    uint32_t a;
    asm("{ .reg .u64 t; cvta.to.shared.u64 t, %1; cvt.u32.u64 %0, t; }"
        : "=r"(a) : "l"(p));
    return a;
}

__device__ __forceinline__ void mma_tf32(float* d, const uint32_t* a, const uint32_t* b) {
    asm volatile(
        "mma.sync.aligned.m16n8k8.row.col.f32.tf32.tf32.f32 "
        "{%0,%1,%2,%3}, {%4,%5,%6,%7}, {%8,%9}, {%0,%1,%2,%3};"
        : "+f"(d[0]), "+f"(d[1]), "+f"(d[2]), "+f"(d[3])
        : "r"(a[0]), "r"(a[1]), "r"(a[2]), "r"(a[3]), "r"(b[0]), "r"(b[1]));
}

__device__ __forceinline__ void mma_tf32_b(float* d, const uint32_t* a,
                                           uint32_t b0, uint32_t b1) {
    asm volatile(
        "mma.sync.aligned.m16n8k8.row.col.f32.tf32.tf32.f32 "
        "{%0,%1,%2,%3}, {%4,%5,%6,%7}, {%8,%9}, {%0,%1,%2,%3};"
        : "+f"(d[0]), "+f"(d[1]), "+f"(d[2]), "+f"(d[3])
        : "r"(a[0]), "r"(a[1]), "r"(a[2]), "r"(a[3]), "r"(b0), "r"(b1));
}

__device__ __forceinline__ void ldsm_x4(uint32_t* r, uint32_t addr) {
    asm volatile("ldmatrix.sync.aligned.m8n8.x4.shared.b16 {%0,%1,%2,%3}, [%4];"
        : "=r"(r[0]), "=r"(r[1]), "=r"(r[2]), "=r"(r[3]) : "r"(addr));
}
__device__ __forceinline__ void ldsm_x2(uint32_t* r, uint32_t addr) {
    asm volatile("ldmatrix.sync.aligned.m8n8.x2.shared.b16 {%0,%1}, [%2];"
        : "=r"(r[0]), "=r"(r[1]) : "r"(addr));
}
__device__ __forceinline__ void cp16(uint32_t smaddr, const void* g) {
    asm volatile("cp.async.cg.shared.global [%0], [%1], 16;" :: "r"(smaddr), "l"(g));
}
#define CP_COMMIT() asm volatile("cp.async.commit_group;" ::: "memory")
#define CP_WAIT2()  asm volatile("cp.async.wait_group 2;" ::: "memory")

// ---------------------------------------------------------------------------
// Pre-round GEMM operands to tf32 (rna): segments 0..2 = Q,K,V; 3..6 = weights
// ---------------------------------------------------------------------------
__global__ void round_pass(const float* __restrict__ Q, const float* __restrict__ K,
                           const float* __restrict__ V, const float* __restrict__ wq,
                           const float* __restrict__ wk, const float* __restrict__ wv,
                           const float* __restrict__ wo)
{
    const int seg = blockIdx.y;
    const float* src;
    float* dst;
    int n4;
    if (seg == 0)      { src = Q;  dst = g_aq;               n4 = Mtot * Dd / 4; }
    else if (seg == 1) { src = K;  dst = g_ak;               n4 = Mtot * Dd / 4; }
    else if (seg == 2) { src = V;  dst = g_av;               n4 = Mtot * Dd / 4; }
    else               { src = (seg == 3) ? wq : (seg == 4) ? wk : (seg == 5) ? wv : wo;
                         dst = g_rw + (size_t)(seg - 3) * Dd * Dd;
                         n4 = Dd * Dd / 4; }
    const int stride = gridDim.x * blockDim.x;
    for (int i = blockIdx.x * blockDim.x + threadIdx.x; i < n4; i += stride) {
        float4 v = ((const float4*)src)[i];
        uint4 r;
        r.x = cvt_tf32(v.x); r.y = cvt_tf32(v.y);
        r.z = cvt_tf32(v.z); r.w = cvt_tf32(v.w);
        ((uint4*)dst)[i] = r;
    }
}

// ---------------------------------------------------------------------------
// tf32 mma.sync GEMM, cp.async 3-stage + ldmatrix.
// out[m,n] = sum_k A[m,k]*W[n,k] (+bias). M=4096,N=1024,K=1024.
// CTA 128x128x32, 8 warps (2x4), warp 64x32.
// Stage = A 16KB + B 16KB raw tf32 rows, 16B-chunk swizzle:
//   off(row, c4) = row*128 + ((c4 ^ (row&7))<<4)
// ---------------------------------------------------------------------------
#define GEMM_SMEM_BYTES (3 * 32768)

__device__ __forceinline__ void gemm_body(const float* __restrict__ A,
                                          const float* __restrict__ W,
                                          const float* __restrict__ bias,
                                          float* __restrict__ out,
                                          bool remap)
{
    extern __shared__ char smraw[];
    const uint32_t sb = smem_u32(smraw);

    const int tid  = threadIdx.x;
    const int lane = tid & 31;
    const int wid  = tid >> 5;
    const int wm   = wid >> 2;          // 0..1
    const int wn   = wid & 3;           // 0..3
    const int g    = lane >> 2;
    const int tg   = lane & 3;

    const int m0 = blockIdx.y * 128;
    const int n0 = blockIdx.x * 128;

    // copy mapping: rows rowb+32j, 16B chunk c4, swizzled slot
    const int rowb = tid >> 3;          // 0..31
    const int c4   = tid & 7;
    const uint32_t swz16 = (uint32_t)((c4 ^ (rowb & 7)) << 4);
    const float* Ap = A + (size_t)(m0 + rowb) * 1024 + c4 * 4;
    const float* Wp = W + (size_t)(n0 + rowb) * 1024 + c4 * 4;

    // ldmatrix per-lane address pieces
    const uint32_t aRow = (uint32_t)(wm * 64 + (lane & 15));
    const uint32_t bRow = (uint32_t)(wn * 32 + (lane & 7));
    const uint32_t aHi  = (uint32_t)(lane >> 4);         // 0/1
    const uint32_t bHi  = (uint32_t)((lane >> 3) & 1);   // 0/1
    const uint32_t lsw  = (uint32_t)(lane & 7);

    float acc[4][4][4];
#pragma unroll
    for (int mt = 0; mt < 4; mt++)
#pragma unroll
        for (int nt = 0; nt < 4; nt++)
#pragma unroll
            for (int r = 0; r < 4; r++) acc[mt][nt][r] = 0.0f;

    auto issue = [&](int kt) {
        if (kt < 32) {
            const uint32_t stb = sb + (uint32_t)(kt % 3) * 32768u;
#pragma unroll
            for (int j = 0; j < 4; j++) {
                const int row = rowb + 32 * j;
                const uint32_t d = stb + (uint32_t)(row * 128) + swz16;
                cp16(d,          Ap + (size_t)kt * 32 + (size_t)j * 32768);
                cp16(d + 16384u, Wp + (size_t)kt * 32 + (size_t)j * 32768);
            }
        }
        CP_COMMIT();
    };

    issue(0); issue(1); issue(2);

    for (int kt = 0; kt < 32; kt++) {
        CP_WAIT2();
        __syncthreads();

        const uint32_t stb = sb + (uint32_t)(kt % 3) * 32768u;
        const uint32_t aBase = stb + aRow * 128u;
        const uint32_t bBase = stb + 16384u + bRow * 128u;

#pragma unroll
        for (int ks = 0; ks < 4; ks++) {
            const uint32_t aSw = (((uint32_t)(2 * ks) + aHi) ^ lsw) << 4;
            const uint32_t bSw = (((uint32_t)(2 * ks) + bHi) ^ lsw) << 4;
            uint32_t af[4][4];
#pragma unroll
            for (int mt = 0; mt < 4; mt++)
                ldsm_x4(af[mt], aBase + (uint32_t)(mt * 2048) + aSw);
            uint32_t bf[4][2];
#pragma unroll
            for (int nt = 0; nt < 4; nt++)
                ldsm_x2(bf[nt], bBase + (uint32_t)(nt * 1024) + bSw);
#pragma unroll
            for (int mt = 0; mt < 4; mt++)
#pragma unroll
                for (int nt = 0; nt < 4; nt++)
                    mma_tf32(acc[mt][nt], af[mt], bf[nt]);
        }

        __syncthreads();
        issue(kt + 3);
    }

    // epilogue
#pragma unroll
    for (int mt = 0; mt < 4; mt++) {
#pragma unroll
        for (int nt = 0; nt < 4; nt++) {
            const int m = m0 + wm * 64 + mt * 16 + g;
            const int n = n0 + wn * 32 + nt * 8 + tg * 2;
            float2 lo = make_float2(acc[mt][nt][0], acc[mt][nt][1]);
            float2 hi = make_float2(acc[mt][nt][2], acc[mt][nt][3]);
            if (remap) {
                const int h  = n >> 6;
                const int hd = n & 63;
                const int b0_ = m >> 11,       l0 = m & 2047;
                const int b1_ = (m + 8) >> 11, l1 = (m + 8) & 2047;
                *(float2*)(out + (((size_t)(b0_ * Hh + h) * Ll + l0) * HDd + hd)) = lo;
                *(float2*)(out + (((size_t)(b1_ * Hh + h) * Ll + l1) * HDd + hd)) = hi;
            } else {
                float2 bb = make_float2(bias[n], bias[n + 1]);
                lo.x += bb.x; lo.y += bb.y; hi.x += bb.x; hi.y += bb.y;
                *(float2*)(out + (size_t)m * 1024 + n) = lo;
                *(float2*)(out + (size_t)(m + 8) * 1024 + n) = hi;
            }
        }
    }
}

__global__ __launch_bounds__(256, 2)
void gemm_qkv()
{
    const int z = blockIdx.z;
    const float* A = (z == 0) ? g_aq : (z == 1) ? g_ak : g_av;
    const float* W = g_rw + (size_t)z * Dd * Dd;
    float* out = (z == 0) ? g_q : (z == 1) ? g_k : g_v;
    gemm_body(A, W, nullptr, out, true);
}

__global__ __launch_bounds__(256, 2)
void gemm_o(const float* __restrict__ bo, float* __restrict__ out)
{
    gemm_body(g_ctx, g_rw + (size_t)3 * Dd * Dd, bo, out, false);
}

// ---------------------------------------------------------------------------
// Tensor-core flash attention (causal), 3-term compensated tf32.
// (unchanged from R4 except ctx is written tf32-rounded)
// ---------------------------------------------------------------------------
#define FLASH_SMEM_BYTES 65536

__global__ __launch_bounds__(128)
void flash_tc()
{
    extern __shared__ uint32_t fs[];
    uint32_t* Kh = fs;
    uint32_t* Kl = fs + 4096;
    uint32_t* Vh = fs + 8192;
    uint32_t* Vl = fs + 12288;

    const int tid  = threadIdx.x;
    const int lane = tid & 31;
    const int w    = tid >> 5;
    const int g    = lane >> 2;
    const int tg   = lane & 3;

    const int qb = 31 - blockIdx.x;
    const int q0 = qb * 64;
    const int bh = blockIdx.y;
    const int b  = bh >> 4;
    const int h  = bh & (Hh - 1);

    const float* qp = g_q + (size_t)bh * Ll * HDd;
    const float* kp = g_k + (size_t)bh * Ll * HDd;
    const float* vp = g_v + (size_t)bh * Ll * HDd;

    uint32_t qh[8][4], ql[8][4];
    {
        const float* q0p = qp + (size_t)(q0 + w * 16) * HDd;
#pragma unroll
        for (int dc = 0; dc < 8; dc++) {
            float v0 = q0p[g * 64 + dc * 8 + tg];
            float v1 = q0p[(g + 8) * 64 + dc * 8 + tg];
            float v2 = q0p[g * 64 + dc * 8 + tg + 4];
            float v3 = q0p[(g + 8) * 64 + dc * 8 + tg + 4];
            qh[dc][0] = cvt_tf32(v0); ql[dc][0] = cvt_tf32(v0 - __uint_as_float(qh[dc][0]));
            qh[dc][1] = cvt_tf32(v1); ql[dc][1] = cvt_tf32(v1 - __uint_as_float(qh[dc][1]));
            qh[dc][2] = cvt_tf32(v2); ql[dc][2] = cvt_tf32(v2 - __uint_as_float(qh[dc][2]));
            qh[dc][3] = cvt_tf32(v3); ql[dc][3] = cvt_tf32(v3 - __uint_as_float(qh[dc][3]));
        }
    }

    float m0 = -1e30f, m1 = -1e30f, l0 = 0.0f, l1 = 0.0f;
    float o[8][4];
#pragma unroll
    for (int nt = 0; nt < 8; nt++)
#pragma unroll
        for (int r = 0; r < 4; r++) o[nt][r] = 0.0f;

    const int nT = qb + 1;
    const int row0 = q0 + w * 16 + g;
    const int row1 = row0 + 8;

    for (int kt = 0; kt < nT; kt++) {
        const int j0 = kt * 64;
        __syncthreads();

#pragma unroll
        for (int i = 0; i < 8; i++) {
            const int t  = tid + i * 128;
            const int j  = t >> 4;
            const int cq = t & 15;
            const int d0 = cq * 4;

            float4 kv = *(const float4*)(kp + (size_t)(j0 + j) * 64 + d0);
            float4 vv = *(const float4*)(vp + (size_t)(j0 + j) * 64 + d0);

            {
                const int dc  = cq >> 1;
                const int reg = cq & 1;
                const int gsl = (j & 7) ^ ((reg << 2) | ((dc >> 2) << 1));
                const int base = reg * 2048 + (dc * 8 + (j >> 3)) * 32 + gsl * 4;
                const float kvv[4] = {kv.x, kv.y, kv.z, kv.w};
#pragma unroll
                for (int u = 0; u < 4; u++) {
                    const int idx = base + (u ^ (dc & 3));
                    uint32_t hi = cvt_tf32(kvv[u]);
                    Kh[idx] = hi;
                    Kl[idx] = cvt_tf32(kvv[u] - __uint_as_float(hi));
                }
            }
            {
                const int kc = j >> 3;
                const int rv = (j >> 2) & 1;
                const float vvv[4] = {vv.x, vv.y, vv.z, vv.w};
#pragma unroll
                for (int u = 0; u < 4; u++) {
                    const int d   = d0 + u;
                    const int ntd = d >> 3;
                    const int idx = rv * 2048 + (kc * 8 + ntd) * 32
                                  + (((d & 7) ^ (ntd & 3)) << 2)
                                  + ((j & 3) ^ ((ntd & 4) >> 1));
                    uint32_t hi = cvt_tf32(vvv[u]);
                    Vh[idx] = hi;
                    Vl[idx] = cvt_tf32(vvv[u] - __uint_as_float(hi));
                }
            }
        }
        __syncthreads();

        float sc[8][4];
#pragma unroll
        for (int nt = 0; nt < 8; nt++)
#pragma unroll
            for (int r = 0; r < 4; r++) sc[nt][r] = 0.0f;

#pragma unroll
        for (int dc = 0; dc < 8; dc++) {
            const int tK = tg ^ (dc & 3);
            const int f0 = (dc >> 2) << 1;
            const int i0 = dc * 256 + ((g ^ f0) << 2) + tK;
            const int i1 = 2048 + dc * 256 + ((g ^ (f0 | 4)) << 2) + tK;
#pragma unroll
            for (int nt = 0; nt < 8; nt++) {
                const uint32_t bh0 = Kh[i0 + nt * 32];
                const uint32_t bh1 = Kh[i1 + nt * 32];
                const uint32_t bl0 = Kl[i0 + nt * 32];
                const uint32_t bl1 = Kl[i1 + nt * 32];
                mma_tf32_b(sc[nt], qh[dc], bh0, bh1);
                mma_tf32_b(sc[nt], qh[dc], bl0, bl1);
                mma_tf32_b(sc[nt], ql[dc], bh0, bh1);
            }
        }

        if (kt == nT - 1) {
#pragma unroll
            for (int nt = 0; nt < 8; nt++) {
                const int c0 = j0 + nt * 8 + tg * 2;
                const int c1 = c0 + 1;
                sc[nt][0] = (c0 <= row0) ? sc[nt][0] * SCALE : -1e30f;
                sc[nt][1] = (c1 <= row0) ? sc[nt][1] * SCALE : -1e30f;
                sc[nt][2] = (c0 <= row1) ? sc[nt][2] * SCALE : -1e30f;
                sc[nt][3] = (c1 <= row1) ? sc[nt][3] * SCALE : -1e30f;
            }
        } else {
#pragma unroll
            for (int nt = 0; nt < 8; nt++)
#pragma unroll
                for (int r = 0; r < 4; r++) sc[nt][r] *= SCALE;
        }

        float mx0 = -1e30f, mx1 = -1e30f;
#pragma unroll
        for (int nt = 0; nt < 8; nt++) {
            mx0 = fmaxf(mx0, fmaxf(sc[nt][0], sc[nt][1]));
            mx1 = fmaxf(mx1, fmaxf(sc[nt][2], sc[nt][3]));
        }
        mx0 = fmaxf(mx0, __shfl_xor_sync(0xffffffffu, mx0, 1));
        mx0 = fmaxf(mx0, __shfl_xor_sync(0xffffffffu, mx0, 2));
        mx1 = fmaxf(mx1, __shfl_xor_sync(0xffffffffu, mx1, 1));
        mx1 = fmaxf(mx1, __shfl_xor_sync(0xffffffffu, mx1, 2));

        const float mn0 = fmaxf(m0, mx0);
        const float mn1 = fmaxf(m1, mx1);
        const float a0 = __expf(m0 - mn0);
        const float a1 = __expf(m1 - mn1);

        float s0 = 0.0f, s1 = 0.0f;
#pragma unroll
        for (int nt = 0; nt < 8; nt++) {
            sc[nt][0] = __expf(sc[nt][0] - mn0);
            sc[nt][1] = __expf(sc[nt][1] - mn0);
            sc[nt][2] = __expf(sc[nt][2] - mn1);
            sc[nt][3] = __expf(sc[nt][3] - mn1);
            s0 += sc[nt][0] + sc[nt][1];
            s1 += sc[nt][2] + sc[nt][3];
        }
        s0 += __shfl_xor_sync(0xffffffffu, s0, 1);
        s0 += __shfl_xor_sync(0xffffffffu, s0, 2);
        s1 += __shfl_xor_sync(0xffffffffu, s1, 1);
        s1 += __shfl_xor_sync(0xffffffffu, s1, 2);

        l0 = l0 * a0 + s0;  m0 = mn0;
        l1 = l1 * a1 + s1;  m1 = mn1;

#pragma unroll
        for (int nt = 0; nt < 8; nt++) {
            o[nt][0] *= a0; o[nt][1] *= a0;
            o[nt][2] *= a1; o[nt][3] *= a1;
        }

        const int sAsrc = (lane & ~3) | (tg >> 1);
        const int sBsrc = sAsrc + 2;
#pragma unroll
        for (int kc = 0; kc < 8; kc++) {
            uint32_t ph[4], pl[4];
#pragma unroll
            for (int r = 0; r < 4; r++) {
                ph[r] = cvt_tf32(sc[kc][r]);
                pl[r] = cvt_tf32(sc[kc][r] - __uint_as_float(ph[r]));
            }
            uint32_t ah[4], al[4];
            {
                uint32_t x0, x1;
                x0 = __shfl_sync(0xffffffffu, ph[0], sAsrc);
                x1 = __shfl_sync(0xffffffffu, ph[1], sAsrc);
                ah[0] = (tg & 1) ? x1 : x0;
                x0 = __shfl_sync(0xffffffffu, ph[2], sAsrc);
                x1 = __shfl_sync(0xffffffffu, ph[3], sAsrc);
                ah[1] = (tg & 1) ? x1 : x0;
                x0 = __shfl_sync(0xffffffffu, ph[0], sBsrc);
                x1 = __shfl_sync(0xffffffffu, ph[1], sBsrc);
                ah[2] = (tg & 1) ? x1 : x0;
                x0 = __shfl_sync(0xffffffffu, ph[2], sBsrc);
                x1 = __shfl_sync(0xffffffffu, ph[3], sBsrc);
                ah[3] = (tg & 1) ? x1 : x0;

                x0 = __shfl_sync(0xffffffffu, pl[0], sAsrc);
                x1 = __shfl_sync(0xffffffffu, pl[1], sAsrc);
                al[0] = (tg & 1) ? x1 : x0;
                x0 = __shfl_sync(0xffffffffu, pl[2], sAsrc);
                x1 = __shfl_sync(0xffffffffu, pl[3], sAsrc);
                al[1] = (tg & 1) ? x1 : x0;
                x0 = __shfl_sync(0xffffffffu, pl[0], sBsrc);
                x1 = __shfl_sync(0xffffffffu, pl[1], sBsrc);
                al[2] = (tg & 1) ? x1 : x0;
                x0 = __shfl_sync(0xffffffffu, pl[2], sBsrc);
                x1 = __shfl_sync(0xffffffffu, pl[3], sBsrc);
                al[3] = (tg & 1) ? x1 : x0;
            }
#pragma unroll
            for (int ntd = 0; ntd < 8; ntd++) {
                const int lv = ((g ^ (ntd & 3)) << 2) + (tg ^ ((ntd & 4) >> 1));
                const int i0 = kc * 256 + ntd * 32 + lv;
                const uint32_t bh0 = Vh[i0];
                const uint32_t bh1 = Vh[2048 + i0];
                const uint32_t bl0 = Vl[i0];
                const uint32_t bl1 = Vl[2048 + i0];
                mma_tf32_b(o[ntd], ah, bh0, bh1);
                mma_tf32_b(o[ntd], ah, bl0, bl1);
                mma_tf32_b(o[ntd], al, bh0, bh1);
            }
        }
    }

    // normalize & write ctx (tf32-rounded so gemm_o consumes exact tf32)
    const float inv0 = 1.0f / l0;
    const float inv1 = 1.0f / l1;
    float* c0p = g_ctx + ((size_t)b * Ll + row0) * Dd + h * 64;
    float* c1p = g_ctx + ((size_t)b * Ll + row1) * Dd + h * 64;
#pragma unroll
    for (int nt = 0; nt < 8; nt++) {
        float2 r0 = make_float2(__uint_as_float(cvt_tf32(o[nt][0] * inv0)),
                                __uint_as_float(cvt_tf32(o[nt][1] * inv0)));
        float2 r1 = make_float2(__uint_as_float(cvt_tf32(o[nt][2] * inv1)),
                                __uint_as_float(cvt_tf32(o[nt][3] * inv1)));
        *(float2*)(c0p + nt * 8 + tg * 2) = r0;
        *(float2*)(c1p + nt * 8 + tg * 2) = r1;
    }
}

// ---------------------------------------------------------------------------
// Launch
// ---------------------------------------------------------------------------
extern "C" void kernel_launch(void* const* d_in, const int* in_sizes, int n_in,
                              void* d_out, int out_size)
{
    const float* Q  = (const float*)d_in[0];
    const float* K  = (const float*)d_in[1];
    const float* V  = (const float*)d_in[2];
    // d_in[3] = mask (causal tril, applied analytically)
    const float* wq = (const float*)d_in[4];
    const float* wk = (const float*)d_in[5];
    const float* wv = (const float*)d_in[6];
    const float* wo = (const float*)d_in[7];
    const float* bo = (const float*)d_in[8];
    float* out = (float*)d_out;

    cudaFuncSetAttribute(gemm_qkv, cudaFuncAttributeMaxDynamicSharedMemorySize, GEMM_SMEM_BYTES);
    cudaFuncSetAttribute(gemm_o,   cudaFuncAttributeMaxDynamicSharedMemorySize, GEMM_SMEM_BYTES);
    cudaFuncSetAttribute(flash_tc, cudaFuncAttributeMaxDynamicSharedMemorySize, FLASH_SMEM_BYTES);

    round_pass<<<dim3(512, 7), 256>>>(Q, K, V, wq, wk, wv, wo);

    gemm_qkv<<<dim3(8, 32, 3), 256, GEMM_SMEM_BYTES>>>();

    flash_tc<<<dim3(32, 32), 128, FLASH_SMEM_BYTES>>>();

    gemm_o<<<dim3(8, 32), 256, GEMM_SMEM_BYTES>>>(bo, out);
}

// round 6
// speedup vs baseline: 3.9434x; 1.4533x over previous
#include <cuda_runtime.h>
#include <cuda_bf16.h>
#include <math.h>
#include <cstdint>

// Problem constants
#define Bb   2
#define Ll   2048
#define Dd   1024
#define Hh   16
#define HDd  64
#define Mtot (Bb * Ll)          // 4096
#define SCALE 0.125f            // 1/sqrt(64)

// Scratch
__device__ float g_ctx[(size_t)Bb * Ll * Dd];
// tf32-prerounded GEMM operands
__device__ float g_aq[(size_t)Mtot * Dd];
__device__ float g_ak[(size_t)Mtot * Dd];
__device__ float g_av[(size_t)Mtot * Dd];
__device__ float g_rw[(size_t)4 * Dd * Dd];
// bf16 hi/lo packed (u32 = 2 bf16 along hd), layout [bh][l][32]
#define QKV_U32 ((size_t)Bb * Hh * Ll * 32)
__device__ uint32_t g_qh[QKV_U32], g_ql[QKV_U32];
__device__ uint32_t g_kh[QKV_U32], g_kl[QKV_U32];
__device__ uint32_t g_vh[QKV_U32], g_vl[QKV_U32];

__device__ __forceinline__ uint32_t cvt_tf32(float x) {
    uint32_t r;
    asm("cvt.rna.tf32.f32 %0, %1;" : "=r"(r) : "f"(x));
    return r;
}

__device__ __forceinline__ uint32_t smem_u32(const void* p) {
    uint32_t a;
    asm("{ .reg .u64 t; cvta.to.shared.u64 t, %1; cvt.u32.u64 %0, t; }"
        : "=r"(a) : "l"(p));
    return a;
}

__device__ __forceinline__ void mma_tf32(float* d, const uint32_t* a, const uint32_t* b) {
    asm volatile(
        "mma.sync.aligned.m16n8k8.row.col.f32.tf32.tf32.f32 "
        "{%0,%1,%2,%3}, {%4,%5,%6,%7}, {%8,%9}, {%0,%1,%2,%3};"
        : "+f"(d[0]), "+f"(d[1]), "+f"(d[2]), "+f"(d[3])
        : "r"(a[0]), "r"(a[1]), "r"(a[2]), "r"(a[3]), "r"(b[0]), "r"(b[1]));
}

__device__ __forceinline__ void mma_bf16(float* d, const uint32_t* a,
                                         uint32_t b0, uint32_t b1) {
    asm volatile(
        "mma.sync.aligned.m16n8k16.row.col.f32.bf16.bf16.f32 "
        "{%0,%1,%2,%3}, {%4,%5,%6,%7}, {%8,%9}, {%0,%1,%2,%3};"
        : "+f"(d[0]), "+f"(d[1]), "+f"(d[2]), "+f"(d[3])
        : "r"(a[0]), "r"(a[1]), "r"(a[2]), "r"(a[3]), "r"(b0), "r"(b1));
}

__device__ __forceinline__ void ldsm_x4(uint32_t* r, uint32_t addr) {
    asm volatile("ldmatrix.sync.aligned.m8n8.x4.shared.b16 {%0,%1,%2,%3}, [%4];"
        : "=r"(r[0]), "=r"(r[1]), "=r"(r[2]), "=r"(r[3]) : "r"(addr));
}
__device__ __forceinline__ void ldsm_x4t(uint32_t* r, uint32_t addr) {
    asm volatile("ldmatrix.sync.aligned.m8n8.x4.trans.shared.b16 {%0,%1,%2,%3}, [%4];"
        : "=r"(r[0]), "=r"(r[1]), "=r"(r[2]), "=r"(r[3]) : "r"(addr));
}
__device__ __forceinline__ void ldsm_x2(uint32_t* r, uint32_t addr) {
    asm volatile("ldmatrix.sync.aligned.m8n8.x2.shared.b16 {%0,%1}, [%2];"
        : "=r"(r[0]), "=r"(r[1]) : "r"(addr));
}
__device__ __forceinline__ void cp16(uint32_t smaddr, const void* g) {
    asm volatile("cp.async.cg.shared.global [%0], [%1], 16;" :: "r"(smaddr), "l"(g));
}
#define CP_COMMIT() asm volatile("cp.async.commit_group;" ::: "memory")
#define CP_WAIT2()  asm volatile("cp.async.wait_group 2;" ::: "memory")
#define CP_WAIT1()  asm volatile("cp.async.wait_group 1;" ::: "memory")

__device__ __forceinline__ void pack_hilo(float x, float y, uint32_t& h, uint32_t& l) {
    __nv_bfloat162 hh = __floats2bfloat162_rn(x, y);
    __nv_bfloat162 ll = __floats2bfloat162_rn(x - __bfloat162float(hh.x),
                                              y - __bfloat162float(hh.y));
    h = *(uint32_t*)&hh;
    l = *(uint32_t*)&ll;
}

// ---------------------------------------------------------------------------
// Pre-round GEMM operands to tf32
// ---------------------------------------------------------------------------
__global__ void round_pass(const float* __restrict__ Q, const float* __restrict__ K,
                           const float* __restrict__ V, const float* __restrict__ wq,
                           const float* __restrict__ wk, const float* __restrict__ wv,
                           const float* __restrict__ wo)
{
    const int seg = blockIdx.y;
    const float* src;
    float* dst;
    int n4;
    if (seg == 0)      { src = Q;  dst = g_aq; n4 = Mtot * Dd / 4; }
    else if (seg == 1) { src = K;  dst = g_ak; n4 = Mtot * Dd / 4; }
    else if (seg == 2) { src = V;  dst = g_av; n4 = Mtot * Dd / 4; }
    else               { src = (seg == 3) ? wq : (seg == 4) ? wk : (seg == 5) ? wv : wo;
                         dst = g_rw + (size_t)(seg - 3) * Dd * Dd;
                         n4 = Dd * Dd / 4; }
    const int stride = gridDim.x * blockDim.x;
    for (int i = blockIdx.x * blockDim.x + threadIdx.x; i < n4; i += stride) {
        float4 v = ((const float4*)src)[i];
        uint4 r;
        r.x = cvt_tf32(v.x); r.y = cvt_tf32(v.y);
        r.z = cvt_tf32(v.z); r.w = cvt_tf32(v.w);
        ((uint4*)dst)[i] = r;
    }
}

// ---------------------------------------------------------------------------
// tf32 mma.sync GEMM, cp.async 3-stage + ldmatrix (from R5).
// remap: out -> packed bf16 hi/lo [bh][l][32]; else f32 [M,N]+bias.
// ---------------------------------------------------------------------------
#define GEMM_SMEM_BYTES (3 * 32768)

__device__ __forceinline__ void gemm_body(const float* __restrict__ A,
                                          const float* __restrict__ W,
                                          const float* __restrict__ bias,
                                          float* __restrict__ outf,
                                          uint32_t* __restrict__ outh,
                                          uint32_t* __restrict__ outl,
                                          bool remap)
{
    extern __shared__ char smraw[];
    const uint32_t sb = smem_u32(smraw);

    const int tid  = threadIdx.x;
    const int lane = tid & 31;
    const int wid  = tid >> 5;
    const int wm   = wid >> 2;
    const int wn   = wid & 3;
    const int g    = lane >> 2;
    const int tg   = lane & 3;

    const int m0 = blockIdx.y * 128;
    const int n0 = blockIdx.x * 128;

    const int rowb = tid >> 3;
    const int c4   = tid & 7;
    const uint32_t swz16 = (uint32_t)((c4 ^ (rowb & 7)) << 4);
    const float* Ap = A + (size_t)(m0 + rowb) * 1024 + c4 * 4;
    const float* Wp = W + (size_t)(n0 + rowb) * 1024 + c4 * 4;

    const uint32_t aRow = (uint32_t)(wm * 64 + (lane & 15));
    const uint32_t bRow = (uint32_t)(wn * 32 + (lane & 7));
    const uint32_t aHi  = (uint32_t)(lane >> 4);
    const uint32_t bHi  = (uint32_t)((lane >> 3) & 1);
    const uint32_t lsw  = (uint32_t)(lane & 7);

    float acc[4][4][4];
#pragma unroll
    for (int mt = 0; mt < 4; mt++)
#pragma unroll
        for (int nt = 0; nt < 4; nt++)
#pragma unroll
            for (int r = 0; r < 4; r++) acc[mt][nt][r] = 0.0f;

    auto issue = [&](int kt) {
        if (kt < 32) {
            const uint32_t stb = sb + (uint32_t)(kt % 3) * 32768u;
#pragma unroll
            for (int j = 0; j < 4; j++) {
                const int row = rowb + 32 * j;
                const uint32_t d = stb + (uint32_t)(row * 128) + swz16;
                cp16(d,          Ap + (size_t)kt * 32 + (size_t)j * 32768);
                cp16(d + 16384u, Wp + (size_t)kt * 32 + (size_t)j * 32768);
            }
        }
        CP_COMMIT();
    };

    issue(0); issue(1); issue(2);

    for (int kt = 0; kt < 32; kt++) {
        CP_WAIT2();
        __syncthreads();

        const uint32_t stb = sb + (uint32_t)(kt % 3) * 32768u;
        const uint32_t aBase = stb + aRow * 128u;
        const uint32_t bBase = stb + 16384u + bRow * 128u;

#pragma unroll
        for (int ks = 0; ks < 4; ks++) {
            const uint32_t aSw = (((uint32_t)(2 * ks) + aHi) ^ lsw) << 4;
            const uint32_t bSw = (((uint32_t)(2 * ks) + bHi) ^ lsw) << 4;
            uint32_t af[4][4];
#pragma unroll
            for (int mt = 0; mt < 4; mt++)
                ldsm_x4(af[mt], aBase + (uint32_t)(mt * 2048) + aSw);
            uint32_t bf[4][2];
#pragma unroll
            for (int nt = 0; nt < 4; nt++)
                ldsm_x2(bf[nt], bBase + (uint32_t)(nt * 1024) + bSw);
#pragma unroll
            for (int mt = 0; mt < 4; mt++)
#pragma unroll
                for (int nt = 0; nt < 4; nt++)
                    mma_tf32(acc[mt][nt], af[mt], bf[nt]);
        }

        __syncthreads();
        issue(kt + 3);
    }

#pragma unroll
    for (int mt = 0; mt < 4; mt++) {
#pragma unroll
        for (int nt = 0; nt < 4; nt++) {
            const int m = m0 + wm * 64 + mt * 16 + g;
            const int n = n0 + wn * 32 + nt * 8 + tg * 2;
            float2 lo = make_float2(acc[mt][nt][0], acc[mt][nt][1]);
            float2 hi = make_float2(acc[mt][nt][2], acc[mt][nt][3]);
            if (remap) {
                const int h  = n >> 6;
                const int p  = (n & 63) >> 1;
                const int b0_ = m >> 11,       l0 = m & 2047;
                const int b1_ = (m + 8) >> 11, l1 = (m + 8) & 2047;
                const size_t i0 = ((size_t)(b0_ * Hh + h) * Ll + l0) * 32 + p;
                const size_t i1 = ((size_t)(b1_ * Hh + h) * Ll + l1) * 32 + p;
                uint32_t hA, lA;
                pack_hilo(lo.x, lo.y, hA, lA);
                outh[i0] = hA; outl[i0] = lA;
                pack_hilo(hi.x, hi.y, hA, lA);
                outh[i1] = hA; outl[i1] = lA;
            } else {
                float2 bb = make_float2(bias[n], bias[n + 1]);
                lo.x += bb.x; lo.y += bb.y; hi.x += bb.x; hi.y += bb.y;
                *(float2*)(outf + (size_t)m * 1024 + n) = lo;
                *(float2*)(outf + (size_t)(m + 8) * 1024 + n) = hi;
            }
        }
    }
}

__global__ __launch_bounds__(256, 2)
void gemm_qkv()
{
    const int z = blockIdx.z;
    const float* A = (z == 0) ? g_aq : (z == 1) ? g_ak : g_av;
    const float* W = g_rw + (size_t)z * Dd * Dd;
    uint32_t* oh = (z == 0) ? g_qh : (z == 1) ? g_kh : g_vh;
    uint32_t* ol = (z == 0) ? g_ql : (z == 1) ? g_kl : g_vl;
    gemm_body(A, W, nullptr, nullptr, oh, ol, true);
}

__global__ __launch_bounds__(256, 2)
void gemm_o(const float* __restrict__ bo, float* __restrict__ out)
{
    gemm_body(g_ctx, g_rw + (size_t)3 * Dd * Dd, bo, out, nullptr, nullptr, false);
}

// ---------------------------------------------------------------------------
// bf16 hi/lo 3-term flash attention (causal), m16n8k16 mma.sync.
// Grid (16 qblocks heavy-first, 32 bh), 256 threads (8 warps).
// BM=128 (warp w owns rows q0+w*16..+15), BN=64.
// Smem: 2 stages x [Khi|Klo|Vhi|Vlo], each 64 rows x 32 u32 (8KB), 64KB total.
// Swizzle: 16B chunk ch stored at slot ch ^ (row & 7).
// ---------------------------------------------------------------------------
#define FLASH_SMEM_BYTES 65536

__global__ __launch_bounds__(256)
void flash_bf16()
{
    extern __shared__ uint32_t fs[];
    const uint32_t sb = smem_u32(fs);

    const int tid  = threadIdx.x;
    const int lane = tid & 31;
    const int w    = tid >> 5;
    const int g    = lane >> 2;
    const int tg   = lane & 3;

    const int qb = 15 - blockIdx.x;     // heavy blocks first
    const int q0 = qb * 128;
    const int bh = blockIdx.y;
    const int b  = bh >> 4;
    const int h  = bh & (Hh - 1);

    const uint32_t* qhp = g_qh + (size_t)bh * Ll * 32;
    const uint32_t* qlp = g_ql + (size_t)bh * Ll * 32;
    const uint32_t* khp = g_kh + (size_t)bh * Ll * 32;
    const uint32_t* klp = g_kl + (size_t)bh * Ll * 32;
    const uint32_t* vhp = g_vh + (size_t)bh * Ll * 32;
    const uint32_t* vlp = g_vl + (size_t)bh * Ll * 32;

    const int row0 = q0 + w * 16 + g;
    const int row1 = row0 + 8;

    // ---- Q fragments (register-resident, bf16 hi/lo) ----
    uint32_t qa_h[4][4], qa_l[4][4];
#pragma unroll
    for (int kb = 0; kb < 4; kb++) {
        qa_h[kb][0] = qhp[(size_t)row0 * 32 + kb * 8 + tg];
        qa_h[kb][1] = qhp[(size_t)row1 * 32 + kb * 8 + tg];
        qa_h[kb][2] = qhp[(size_t)row0 * 32 + kb * 8 + tg + 4];
        qa_h[kb][3] = qhp[(size_t)row1 * 32 + kb * 8 + tg + 4];
        qa_l[kb][0] = qlp[(size_t)row0 * 32 + kb * 8 + tg];
        qa_l[kb][1] = qlp[(size_t)row1 * 32 + kb * 8 + tg];
        qa_l[kb][2] = qlp[(size_t)row0 * 32 + kb * 8 + tg + 4];
        qa_l[kb][3] = qlp[(size_t)row1 * 32 + kb * 8 + tg + 4];
    }

    float m0 = -1e30f, m1 = -1e30f, l0s = 0.0f, l1s = 0.0f;
    float o[8][4];
#pragma unroll
    for (int dt = 0; dt < 8; dt++)
#pragma unroll
        for (int r = 0; r < 4; r++) o[dt][r] = 0.0f;

    const int nT = 2 * qb + 2;

    // cp.async loader: per thread 2 chunks per array (4 arrays)
    const int lrow = tid >> 3;          // 0..31 (+32 on second iter)
    const int lch  = tid & 7;
    auto issue = [&](int kt) {
        if (kt < nT) {
            const uint32_t stb = sb + (uint32_t)(kt & 1) * 32768u;
            const int j0 = kt * 64;
            const uint32_t* srcs[4] = {khp, klp, vhp, vlp};
#pragma unroll
            for (int a = 0; a < 4; a++) {
#pragma unroll
                for (int it = 0; it < 2; it++) {
                    const int row = lrow + it * 32;
                    const int sw  = lch ^ (row & 7);
                    cp16(stb + (uint32_t)(a * 8192 + row * 128 + sw * 16),
                         srcs[a] + (size_t)(j0 + row) * 32 + lch * 4);
                }
            }
        }
        CP_COMMIT();
    };

    issue(0);

    for (int kt = 0; kt < nT; kt++) {
        issue(kt + 1);
        CP_WAIT1();
        __syncthreads();

        const uint32_t stb = sb + (uint32_t)(kt & 1) * 32768u;
        const int j0 = kt * 64;

        // ---- S = Q K^T : 3-term bf16 ----
        float sc[8][4];
#pragma unroll
        for (int nt = 0; nt < 8; nt++)
#pragma unroll
            for (int r = 0; r < 4; r++) sc[nt][r] = 0.0f;

        {
            const int q4 = lane >> 3;           // 0..3 quadrant
            const int r8 = lane & 7;
#pragma unroll
            for (int kb = 0; kb < 4; kb++) {
#pragma unroll
                for (int ntp = 0; ntp < 4; ntp++) {
                    const int nt  = 2 * ntp + (q4 >> 1);
                    const int row = nt * 8 + r8;
                    const int ch  = (2 * kb + (q4 & 1)) ^ r8;
                    const uint32_t ah = stb + (uint32_t)(row * 128 + ch * 16);
                    uint32_t bhr[4], blr[4];
                    ldsm_x4(bhr, ah);
                    ldsm_x4(blr, ah + 8192u);
                    mma_bf16(sc[2 * ntp],     qa_h[kb], bhr[0], bhr[1]);
                    mma_bf16(sc[2 * ntp],     qa_h[kb], blr[0], blr[1]);
                    mma_bf16(sc[2 * ntp],     qa_l[kb], bhr[0], bhr[1]);
                    mma_bf16(sc[2 * ntp + 1], qa_h[kb], bhr[2], bhr[3]);
                    mma_bf16(sc[2 * ntp + 1], qa_h[kb], blr[2], blr[3]);
                    mma_bf16(sc[2 * ntp + 1], qa_l[kb], bhr[2], bhr[3]);
                }
            }
        }

        // ---- scale + causal mask ----
        if (kt >= nT - 2) {
#pragma unroll
            for (int nt = 0; nt < 8; nt++) {
                const int c0 = j0 + nt * 8 + tg * 2;
                const int c1 = c0 + 1;
                sc[nt][0] = (c0 <= row0) ? sc[nt][0] * SCALE : -1e30f;
                sc[nt][1] = (c1 <= row0) ? sc[nt][1] * SCALE : -1e30f;
                sc[nt][2] = (c0 <= row1) ? sc[nt][2] * SCALE : -1e30f;
                sc[nt][3] = (c1 <= row1) ? sc[nt][3] * SCALE : -1e30f;
            }
        } else {
#pragma unroll
            for (int nt = 0; nt < 8; nt++)
#pragma unroll
                for (int r = 0; r < 4; r++) sc[nt][r] *= SCALE;
        }

        // ---- online softmax ----
        float mx0 = -1e30f, mx1 = -1e30f;
#pragma unroll
        for (int nt = 0; nt < 8; nt++) {
            mx0 = fmaxf(mx0, fmaxf(sc[nt][0], sc[nt][1]));
            mx1 = fmaxf(mx1, fmaxf(sc[nt][2], sc[nt][3]));
        }
        mx0 = fmaxf(mx0, __shfl_xor_sync(0xffffffffu, mx0, 1));
        mx0 = fmaxf(mx0, __shfl_xor_sync(0xffffffffu, mx0, 2));
        mx1 = fmaxf(mx1, __shfl_xor_sync(0xffffffffu, mx1, 1));
        mx1 = fmaxf(mx1, __shfl_xor_sync(0xffffffffu, mx1, 2));

        const float mn0 = fmaxf(m0, mx0);
        const float mn1 = fmaxf(m1, mx1);
        const float a0 = __expf(m0 - mn0);
        const float a1 = __expf(m1 - mn1);

        float s0 = 0.0f, s1 = 0.0f;
#pragma unroll
        for (int nt = 0; nt < 8; nt++) {
            sc[nt][0] = __expf(sc[nt][0] - mn0);
            sc[nt][1] = __expf(sc[nt][1] - mn0);
            sc[nt][2] = __expf(sc[nt][2] - mn1);
            sc[nt][3] = __expf(sc[nt][3] - mn1);
            s0 += sc[nt][0] + sc[nt][1];
            s1 += sc[nt][2] + sc[nt][3];
        }
        s0 += __shfl_xor_sync(0xffffffffu, s0, 1);
        s0 += __shfl_xor_sync(0xffffffffu, s0, 2);
        s1 += __shfl_xor_sync(0xffffffffu, s1, 1);
        s1 += __shfl_xor_sync(0xffffffffu, s1, 2);

        l0s = l0s * a0 + s0;  m0 = mn0;
        l1s = l1s * a1 + s1;  m1 = mn1;

#pragma unroll
        for (int dt = 0; dt < 8; dt++) {
            o[dt][0] *= a0; o[dt][1] *= a0;
            o[dt][2] *= a1; o[dt][3] *= a1;
        }

        // ---- O += P V : 3-term bf16 (P frags = C layout, no shuffles) ----
        {
            const int q4 = lane >> 3;
            const int r8 = lane & 7;
#pragma unroll
            for (int jb = 0; jb < 4; jb++) {
                uint32_t pah[4], pal[4];
                pack_hilo(sc[2 * jb][0],     sc[2 * jb][1],     pah[0], pal[0]);
                pack_hilo(sc[2 * jb][2],     sc[2 * jb][3],     pah[1], pal[1]);
                pack_hilo(sc[2 * jb + 1][0], sc[2 * jb + 1][1], pah[2], pal[2]);
                pack_hilo(sc[2 * jb + 1][2], sc[2 * jb + 1][3], pah[3], pal[3]);
#pragma unroll
                for (int dtp = 0; dtp < 4; dtp++) {
                    const int dt   = 2 * dtp + (q4 >> 1);
                    const int rowj = jb * 16 + (q4 & 1) * 8 + r8;
                    const int ch   = dt ^ (rowj & 7);
                    const uint32_t ah = stb + (uint32_t)(16384 + rowj * 128 + ch * 16);
                    uint32_t vhr[4], vlr[4];
                    ldsm_x4t(vhr, ah);
                    ldsm_x4t(vlr, ah + 8192u);
                    mma_bf16(o[2 * dtp],     pah, vhr[0], vhr[1]);
                    mma_bf16(o[2 * dtp],     pah, vlr[0], vlr[1]);
                    mma_bf16(o[2 * dtp],     pal, vhr[0], vhr[1]);
                    mma_bf16(o[2 * dtp + 1], pah, vhr[2], vhr[3]);
                    mma_bf16(o[2 * dtp + 1], pah, vlr[2], vlr[3]);
                    mma_bf16(o[2 * dtp + 1], pal, vhr[2], vhr[3]);
                }
            }
        }
        __syncthreads();
    }

    // ---- normalize & write ctx (tf32-rounded for gemm_o) ----
    const float inv0 = 1.0f / l0s;
    const float inv1 = 1.0f / l1s;
    float* c0p = g_ctx + ((size_t)b * Ll + row0) * Dd + h * 64;
    float* c1p = g_ctx + ((size_t)b * Ll + row1) * Dd + h * 64;
#pragma unroll
    for (int dt = 0; dt < 8; dt++) {
        float2 r0 = make_float2(__uint_as_float(cvt_tf32(o[dt][0] * inv0)),
                                __uint_as_float(cvt_tf32(o[dt][1] * inv0)));
        float2 r1 = make_float2(__uint_as_float(cvt_tf32(o[dt][2] * inv1)),
                                __uint_as_float(cvt_tf32(o[dt][3] * inv1)));
        *(float2*)(c0p + dt * 8 + tg * 2) = r0;
        *(float2*)(c1p + dt * 8 + tg * 2) = r1;
    }
}

// ---------------------------------------------------------------------------
// Launch
// ---------------------------------------------------------------------------
extern "C" void kernel_launch(void* const* d_in, const int* in_sizes, int n_in,
                              void* d_out, int out_size)
{
    const float* Q  = (const float*)d_in[0];
    const float* K  = (const float*)d_in[1];
    const float* V  = (const float*)d_in[2];
    // d_in[3] = mask (causal tril, applied analytically)
    const float* wq = (const float*)d_in[4];
    const float* wk = (const float*)d_in[5];
    const float* wv = (const float*)d_in[6];
    const float* wo = (const float*)d_in[7];
    const float* bo = (const float*)d_in[8];
    float* out = (float*)d_out;

    cudaFuncSetAttribute(gemm_qkv,   cudaFuncAttributeMaxDynamicSharedMemorySize, GEMM_SMEM_BYTES);
    cudaFuncSetAttribute(gemm_o,     cudaFuncAttributeMaxDynamicSharedMemorySize, GEMM_SMEM_BYTES);
    cudaFuncSetAttribute(flash_bf16, cudaFuncAttributeMaxDynamicSharedMemorySize, FLASH_SMEM_BYTES);

    round_pass<<<dim3(512, 7), 256>>>(Q, K, V, wq, wk, wv, wo);

    gemm_qkv<<<dim3(8, 32, 3), 256, GEMM_SMEM_BYTES>>>();

    flash_bf16<<<dim3(16, 32), 256, FLASH_SMEM_BYTES>>>();

    gemm_o<<<dim3(8, 32), 256, GEMM_SMEM_BYTES>>>(bo, out);
}